// round 9
// baseline (speedup 1.0000x reference)
#include <cuda_runtime.h>
#include <cuda_bf16.h>
#include <math.h>
#include <stdint.h>

#define NN      6000
#define DD      128
#define RR      1000
#define MAXDEG  128
#define MAXRDEG 64
#define NB      12000     /* 2*NN: both branches stacked */
#define NWB     1500      /* NB/8 warp-per-row grid */
#define MAXN_   0.996f    /* 1 - 4e-3 */

/* ------------------------- static scratch (no allocs) ------------------------- */
__device__ __align__(16) float g_seq[(long)NB*3*DD];       /* [n][l][d] */
__device__ __align__(16) float g_mix[(long)NB*2*DD];       /* [n][h*128+d] x-space mixed */
__device__ __align__(16) float g_mv [(long)NB*DD];         /* GAT layer pre-activation */
__device__ float g_es0[NB], g_ed0[NB], g_es1[NB], g_ed1[NB];
__device__ __align__(16) float g_y2[(long)NB*3*2*DD];      /* y = x @ G */
__device__ __align__(16) float g_z [(long)NB*3*2*DD];      /* attn-mixed x, per head */
__device__ __align__(16) float g_of[(long)NB*3*DD];
__device__ __align__(16) float g_u [(long)NB*DD];
__device__ __align__(16) float g_t [(long)NB*DD];
__device__ __align__(16) float g_y [(long)NB*DD];
__device__ __align__(16) float g_w [(long)NB*DD];
__device__ __align__(16) float g_Gt [2*DD*DD];             /* [t=h*128+d2][d1] */
__device__ __align__(16) float g_Pt [DD*2*DD];             /* [d2][hd] */
__device__ __align__(16) float g_Wgt[2*DD*2*DD];           /* [L][e][h*128+d] */
__device__ __align__(16) float g_wsd[2*2*2*DD];            /* [L][s][h][d] */
__device__ int g_adj_cols[(long)NB*MAXDEG];
__device__ int g_adj_deg[NB];
__device__ int g_rel_cols[(long)NB*MAXRDEG];
__device__ int g_rel_deg[NB];

/* ------------------------- warp helpers --------------------------------------- */
__device__ __forceinline__ float wrsum(float x) {
#pragma unroll
    for (int o = 16; o; o >>= 1) x += __shfl_xor_sync(0xffffffffu, x, o);
    return x;
}
__device__ __forceinline__ float wrmax(float x) {
#pragma unroll
    for (int o = 16; o; o >>= 1) x = fmaxf(x, __shfl_xor_sync(0xffffffffu, x, o));
    return x;
}
__device__ __forceinline__ float dot4(float4 a, float4 b) {
    return a.x*b.x + a.y*b.y + a.z*b.z + a.w*b.w;
}

/* ------------------------- CSR builders --------------------------------------- */
__global__ void k_build_adj(const float* __restrict__ a0, const float* __restrict__ a1) {
    int row = blockIdx.x, b = blockIdx.y;
    const float4* adj = (const float4*)((b ? a1 : a0) + (long)row * NN);
    __shared__ int cnt;
    if (threadIdx.x == 0) cnt = 0;
    __syncthreads();
    int* mc = g_adj_cols + (long)(b*NN + row) * MAXDEG;
    for (int c = threadIdx.x; c < NN/4; c += blockDim.x) {
        float4 v = adj[c];
        if (v.x > 0.f) { int p = atomicAdd(&cnt, 1); if (p < MAXDEG) mc[p] = c*4;   }
        if (v.y > 0.f) { int p = atomicAdd(&cnt, 1); if (p < MAXDEG) mc[p] = c*4+1; }
        if (v.z > 0.f) { int p = atomicAdd(&cnt, 1); if (p < MAXDEG) mc[p] = c*4+2; }
        if (v.w > 0.f) { int p = atomicAdd(&cnt, 1); if (p < MAXDEG) mc[p] = c*4+3; }
    }
    __syncthreads();
    if (threadIdx.x == 0) g_adj_deg[b*NN + row] = min(cnt, MAXDEG);
}
__global__ void k_build_rel(const float* __restrict__ a0, const float* __restrict__ a1) {
    int row = blockIdx.x, b = blockIdx.y;
    const float4* adj = (const float4*)((b ? a1 : a0) + (long)row * RR);
    __shared__ int cnt;
    if (threadIdx.x == 0) cnt = 0;
    __syncthreads();
    int* mc = g_rel_cols + (long)(b*NN + row) * MAXRDEG;
    for (int c = threadIdx.x; c < RR/4; c += blockDim.x) {
        float4 v = adj[c];
        if (v.x > 0.f) { int p = atomicAdd(&cnt, 1); if (p < MAXRDEG) mc[p] = c*4;   }
        if (v.y > 0.f) { int p = atomicAdd(&cnt, 1); if (p < MAXRDEG) mc[p] = c*4+1; }
        if (v.z > 0.f) { int p = atomicAdd(&cnt, 1); if (p < MAXRDEG) mc[p] = c*4+2; }
        if (v.w > 0.f) { int p = atomicAdd(&cnt, 1); if (p < MAXRDEG) mc[p] = c*4+3; }
    }
    __syncthreads();
    if (threadIdx.x == 0) g_rel_deg[b*NN + row] = min(cnt, MAXRDEG);
}

/* ------------------------- rel aggregator (warp/row) -------------------------- */
__global__ __launch_bounds__(256) void k_relagg(const float* __restrict__ r0,
                                                const float* __restrict__ r1,
                                                float* __restrict__ out) {
    int w = blockIdx.x*8 + (threadIdx.x >> 5);
    if (w >= NB) return;
    int lane = threadIdx.x & 31;
    int b = w / NN, row = w - b*NN;
    const float* remb = b ? r1 : r0;
    const int* cols = g_rel_cols + (long)w * MAXRDEG;
    int deg = g_rel_deg[w];
    float4 acc = make_float4(0.f, 0.f, 0.f, 0.f);
    for (int j = 0; j < deg; j++) {
        int c = __ldg(&cols[j]);
        float4 v = *(const float4*)(remb + (long)c*DD + lane*4);
        acc.x += v.x; acc.y += v.y; acc.z += v.z; acc.w += v.w;
    }
    float inv = 1.f / (float)deg;
    float4 r = make_float4(acc.x*inv, acc.y*inv, acc.z*inv, acc.w*inv);
    *(float4*)(out + (long)b*NN*256 + (long)row*256 + 128 + lane*4) = r;
    *(float4*)(out + (long)(2+b)*NN*256 + (long)row*256 + 128 + lane*4) = r;
}

/* ------------------------- seq slot-0 copy + esed(layer0) --------------------- */
__global__ __launch_bounds__(256) void k_seq0e(const float* __restrict__ e0,
                                               const float* __restrict__ e1) {
    int w = blockIdx.x*8 + (threadIdx.x >> 5);
    if (w >= NB) return;
    int lane = threadIdx.x & 31;
    int b = w / NN, row = w - b*NN;
    float4 x4 = *(const float4*)((b ? e1 : e0) + (long)row*DD + lane*4);
    *(float4*)(g_seq + (long)w*384 + lane*4) = x4;
    float4 ws0 = *(const float4*)(g_wsd       + lane*4);
    float4 ws1 = *(const float4*)(g_wsd + 128 + lane*4);
    float4 wd0 = *(const float4*)(g_wsd + 256 + lane*4);
    float4 wd1 = *(const float4*)(g_wsd + 384 + lane*4);
    float v0 = wrsum(dot4(x4, ws0));
    float v1 = wrsum(dot4(x4, wd0));
    float v2 = wrsum(dot4(x4, ws1));
    float v3 = wrsum(dot4(x4, wd1));
    if (lane == 0) { g_es0[w] = v0; g_ed0[w] = v1; g_es1[w] = v2; g_ed1[w] = v3; }
}

/* ------------------------- precompute kernels --------------------------------- */
__global__ void k_precomp_Gt(const float* __restrict__ Wq, const float* __restrict__ Wk) {
    int t = blockIdx.x, d1 = threadIdx.x;
    int h = t >> 7, d2 = t & 127;
    const float* wq = Wq + d1*256 + h*128;
    const float* wk = Wk + d2*256 + h*128;
    float acc = 0.f;
    for (int e = 0; e < 128; e++) acc += wq[e] * wk[e];
    g_Gt[t*128 + d1] = acc;
}
__global__ void k_precomp_Pt(const float* __restrict__ Wv, const float* __restrict__ Wfc) {
    int hd = blockIdx.x, d2 = threadIdx.x;
    int h = hd >> 7, d = hd & 127;
    const float* wv = Wv + d*256 + h*128;
    const float* wf = Wfc + (h*128)*128 + d2;
    float acc = 0.f;
    for (int e = 0; e < 128; e++) acc += wv[e] * wf[e*128];
    g_Pt[d2*256 + hd] = acc;
}
__global__ void k_precomp_gat(const float* __restrict__ W, const float* __restrict__ asrc,
                              const float* __restrict__ adst) {
    int bi = blockIdx.x, d = threadIdx.x;           /* bi = L*4 + s*2 + h */
    int L = bi >> 2, s = (bi >> 1) & 1, h = bi & 1;
    const float* a = (s ? adst : asrc) + (L*2 + h)*128;
    const float* wr = W + (long)((L*2 + h)*128 + d)*128;
    float acc = 0.f;
    for (int e = 0; e < 128; e++) acc += wr[e] * a[e];
    g_wsd[bi*128 + d] = acc;
}
__global__ void k_precomp_Wgt(const float* __restrict__ W) {
    int idx = blockIdx.x*256 + threadIdx.x;        /* 2*2*128*128 */
    if (idx >= 2*2*DD*DD) return;
    int e = idx & 127, d = (idx >> 7) & 127, h = (idx >> 14) & 1, L = idx >> 15;
    g_Wgt[((long)L*128 + e)*256 + h*128 + d] = W[idx];
}

/* ------------------------- bf16-split HMMA GEMM (templated M-tile) ------------
   C[M,N] = A[M,K] @ Bt[N,K]^T, fp32 in/out, 3-pass bf16 hi/lo split.
   K chunk 64. MT=128: 8 warps 4x2 (warp 32x64); MT=64: 2x4 (warp 32x32). ----- */
#define SL 72   /* smem row stride in halfs (64 + 8 pad) */

__device__ __forceinline__ void mma_bf16(float* d, const uint32_t* a,
                                         const uint32_t* b) {
    asm volatile(
        "mma.sync.aligned.m16n8k16.row.col.f32.bf16.bf16.f32 "
        "{%0,%1,%2,%3}, {%4,%5,%6,%7}, {%8,%9}, {%0,%1,%2,%3};"
        : "+f"(d[0]), "+f"(d[1]), "+f"(d[2]), "+f"(d[3])
        : "r"(a[0]), "r"(a[1]), "r"(a[2]), "r"(a[3]), "r"(b[0]), "r"(b[1]));
}

template<int MT>
__global__ void __launch_bounds__(256, 1)
k_hmma(const float* __restrict__ A, int lda,
       const float* __restrict__ Bt, int ldb,
       float* __restrict__ C, int ldc, int M, int K) {
    extern __shared__ __nv_bfloat16 sm[];
    __nv_bfloat16* sAh = sm;
    __nv_bfloat16* sAl = sAh + MT*SL;
    __nv_bfloat16* sBh = sAl + MT*SL;
    __nv_bfloat16* sBl = sBh + 128*SL;
    constexpr int WM = MT/32, WN = 8/WM, NT = 16/WN;
    int tid = threadIdx.x, wid = tid >> 5, lane = tid & 31;
    int wm = wid % WM, wn = wid / WM;
    int g = lane >> 2, tg = lane & 3;
    int bm = blockIdx.y * MT, bn = blockIdx.x * 128;

    float acc[2][NT][4];
#pragma unroll
    for (int i = 0; i < 2; i++)
#pragma unroll
        for (int j = 0; j < NT; j++)
#pragma unroll
            for (int r = 0; r < 4; r++) acc[i][j][r] = 0.f;

    for (int kc = 0; kc < K; kc += 64) {
        /* stage + split: A tile MTx64, B tile 128x64 */
        constexpr int ITERS = (MT + 128) * 16 / 256;
#pragma unroll
        for (int it = 0; it < ITERS; it++) {
            int idx = tid + it*256;
            int r = idx >> 4, c4 = (idx & 15) << 2;
            float4 v;
            __nv_bfloat16 *dh, *dl;
            if (r < MT) {
                int gr = bm + r;
                v = make_float4(0.f, 0.f, 0.f, 0.f);
                if (gr < M) v = *(const float4*)(A + (long)gr*lda + kc + c4);
                dh = sAh + r*SL + c4; dl = sAl + r*SL + c4;
            } else {
                int rr = r - MT;
                v = *(const float4*)(Bt + (long)(bn + rr)*ldb + kc + c4);
                dh = sBh + rr*SL + c4; dl = sBl + rr*SL + c4;
            }
            __nv_bfloat162 h0 = __float22bfloat162_rn(make_float2(v.x, v.y));
            __nv_bfloat162 h1 = __float22bfloat162_rn(make_float2(v.z, v.w));
            float2 f0 = __bfloat1622float2(h0), f1 = __bfloat1622float2(h1);
            __nv_bfloat162 l0 = __float22bfloat162_rn(make_float2(v.x-f0.x, v.y-f0.y));
            __nv_bfloat162 l1 = __float22bfloat162_rn(make_float2(v.z-f1.x, v.w-f1.y));
            *(uint2*)dh = make_uint2(*(uint32_t*)&h0, *(uint32_t*)&h1);
            *(uint2*)dl = make_uint2(*(uint32_t*)&l0, *(uint32_t*)&l1);
        }
        __syncthreads();

#pragma unroll
        for (int ks = 0; ks < 64; ks += 16) {
            uint32_t ah[2][4], al[2][4];
#pragma unroll
            for (int mt = 0; mt < 2; mt++) {
                int r0 = (wm*32 + mt*16 + g) * SL + ks + tg*2;
                int r8 = r0 + 8*SL;
                ah[mt][0] = *(const uint32_t*)&sAh[r0];
                ah[mt][1] = *(const uint32_t*)&sAh[r8];
                ah[mt][2] = *(const uint32_t*)&sAh[r0 + 8];
                ah[mt][3] = *(const uint32_t*)&sAh[r8 + 8];
                al[mt][0] = *(const uint32_t*)&sAl[r0];
                al[mt][1] = *(const uint32_t*)&sAl[r8];
                al[mt][2] = *(const uint32_t*)&sAl[r0 + 8];
                al[mt][3] = *(const uint32_t*)&sAl[r8 + 8];
            }
#pragma unroll
            for (int nt = 0; nt < NT; nt++) {
                int n0 = (wn*NT*8 + nt*8 + g) * SL + ks + tg*2;
                uint32_t bh[2], bl[2];
                bh[0] = *(const uint32_t*)&sBh[n0];
                bh[1] = *(const uint32_t*)&sBh[n0 + 8];
                bl[0] = *(const uint32_t*)&sBl[n0];
                bl[1] = *(const uint32_t*)&sBl[n0 + 8];
                mma_bf16(acc[0][nt], ah[0], bh);
                mma_bf16(acc[1][nt], ah[1], bh);
                mma_bf16(acc[0][nt], ah[0], bl);
                mma_bf16(acc[1][nt], ah[1], bl);
                mma_bf16(acc[0][nt], al[0], bh);
                mma_bf16(acc[1][nt], al[1], bh);
            }
        }
        __syncthreads();
    }

#pragma unroll
    for (int mt = 0; mt < 2; mt++) {
        int r0 = bm + wm*32 + mt*16 + g;
#pragma unroll
        for (int nt = 0; nt < NT; nt++) {
            int c0 = bn + wn*NT*8 + nt*8 + tg*2;
            if (r0 < M)
                *(float2*)(C + (long)r0*ldc + c0) =
                    make_float2(acc[mt][nt][0], acc[mt][nt][1]);
            if (r0 + 8 < M)
                *(float2*)(C + (long)(r0+8)*ldc + c0) =
                    make_float2(acc[mt][nt][2], acc[mt][nt][3]);
        }
    }
}

#define SMEM_128 ((2*128 + 2*128) * SL * 2)   /* 73728 B */
#define SMEM_64  ((2*64  + 2*128) * SL * 2)   /* 55296 B */

/* ------------------------- GAT: softmax-mix in x-space (warp/row) -------------
   0.5 head-mean folded into the softmax normalizers. ---------------------------*/
__global__ __launch_bounds__(256) void k_gat_mix(int L) {
    int w = blockIdx.x*8 + (threadIdx.x >> 5);
    if (w >= NB) return;
    int lane = threadIdx.x & 31;
    int b = w / NN;
    int deg = g_adj_deg[w];
    const int* cols = g_adj_cols + (long)w * MAXDEG;
    int creg[4]; float e0r[4], e1r[4];
    float es0 = g_es0[w], es1 = g_es1[w];
    float m0 = -1e30f, m1 = -1e30f;
#pragma unroll
    for (int i = 0; i < 4; i++) {
        int j = i*32 + lane;
        creg[i] = 0; e0r[i] = -1e30f; e1r[i] = -1e30f;
        if (j < deg) {
            int c = cols[j]; creg[i] = c;
            float t0 = es0 + g_ed0[b*NN + c]; e0r[i] = (t0 > 0.f) ? t0 : 0.2f*t0;
            float t1 = es1 + g_ed1[b*NN + c]; e1r[i] = (t1 > 0.f) ? t1 : 0.2f*t1;
            m0 = fmaxf(m0, e0r[i]); m1 = fmaxf(m1, e1r[i]);
        }
    }
    m0 = wrmax(m0); m1 = wrmax(m1);
    float s0 = 0.f, s1 = 0.f;
    float p0r[4], p1r[4];
#pragma unroll
    for (int i = 0; i < 4; i++) {
        int j = i*32 + lane;
        p0r[i] = (j < deg) ? expf(e0r[i] - m0) : 0.f;
        p1r[i] = (j < deg) ? expf(e1r[i] - m1) : 0.f;
        s0 += p0r[i]; s1 += p1r[i];
    }
    s0 = wrsum(s0); s1 = wrsum(s1);
    float inv0 = 0.5f / s0, inv1 = 0.5f / s1;   /* fold head-mean */
    float4 a0 = make_float4(0.f, 0.f, 0.f, 0.f);
    float4 a1 = make_float4(0.f, 0.f, 0.f, 0.f);
    for (int i = 0; i < 4 && i*32 < deg; i++) {
        for (int l = 0; l < 32; l++) {
            int j = i*32 + l;
            if (j >= deg) break;                    /* uniform across warp */
            int   c  = __shfl_sync(0xffffffffu, creg[i], l);
            float w0 = __shfl_sync(0xffffffffu, p0r[i], l) * inv0;
            float w1 = __shfl_sync(0xffffffffu, p1r[i], l) * inv1;
            float4 x4 = *(const float4*)(g_seq + (long)(b*NN + c)*384 + L*128 + lane*4);
            a0.x += w0*x4.x; a0.y += w0*x4.y; a0.z += w0*x4.z; a0.w += w0*x4.w;
            a1.x += w1*x4.x; a1.y += w1*x4.y; a1.z += w1*x4.z; a1.w += w1*x4.w;
        }
    }
    *(float4*)(g_mix + (long)w*256       + lane*4) = a0;
    *(float4*)(g_mix + (long)w*256 + 128 + lane*4) = a1;
}

/* ------------------ GAT: elu + normalize -> seq slot (+ esed layer1) ---------- */
__global__ __launch_bounds__(256) void k_gat_post(int lslot, int doEsed) {
    int w = blockIdx.x*8 + (threadIdx.x >> 5);
    if (w >= NB) return;
    int lane = threadIdx.x & 31;
    float4 mv = *(const float4*)(g_mv + (long)w*DD + lane*4);
    float4 ev;
    ev.x = (mv.x > 0.f) ? mv.x : expm1f(mv.x);
    ev.y = (mv.y > 0.f) ? mv.y : expm1f(mv.y);
    ev.z = (mv.z > 0.f) ? mv.z : expm1f(mv.z);
    ev.w = (mv.w > 0.f) ? mv.w : expm1f(mv.w);
    float ss = wrsum(dot4(ev, ev));
    float nrm = 1.f / fmaxf(sqrtf(ss), 1e-12f);
    float4 r = make_float4(ev.x*nrm, ev.y*nrm, ev.z*nrm, ev.w*nrm);
    *(float4*)(g_seq + ((long)w*3 + lslot)*DD + lane*4) = r;
    if (doEsed) {
        const float* base = g_wsd + 512;       /* layer-1 vectors */
        float4 ws0 = *(const float4*)(base       + lane*4);
        float4 ws1 = *(const float4*)(base + 128 + lane*4);
        float4 wd0 = *(const float4*)(base + 256 + lane*4);
        float4 wd1 = *(const float4*)(base + 384 + lane*4);
        float v0 = wrsum(dot4(r, ws0));
        float v1 = wrsum(dot4(r, wd0));
        float v2 = wrsum(dot4(r, ws1));
        float v3 = wrsum(dot4(r, wd1));
        if (lane == 0) { g_es0[w] = v0; g_ed0[w] = v1; g_es1[w] = v2; g_ed1[w] = v3; }
    }
}

/* ------------------------- MHA: scores via y.x, mix x (warp/node) ------------- */
__global__ __launch_bounds__(256) void k_mha() {
    int w = blockIdx.x*8 + (threadIdx.x >> 5);
    if (w >= NB) return;
    int lane = threadIdx.x & 31;
    float4 x4[3], y4[3][2];
#pragma unroll
    for (int l = 0; l < 3; l++) {
        x4[l] = *(const float4*)(g_seq + (long)w*384 + l*128 + lane*4);
#pragma unroll
        for (int h = 0; h < 2; h++)
            y4[l][h] = *(const float4*)(g_y2 + (long)w*768 + l*256 + h*128 + lane*4);
    }
    float sc[2][3][3];
#pragma unroll
    for (int h = 0; h < 2; h++)
#pragma unroll
        for (int l = 0; l < 3; l++)
#pragma unroll
            for (int m = 0; m < 3; m++)
                sc[h][l][m] = wrsum(dot4(y4[l][h], x4[m])) * 0.08838834764831845f;
#pragma unroll
    for (int h = 0; h < 2; h++)
#pragma unroll
        for (int l = 0; l < 3; l++) {
            float a0 = sc[h][l][0], a1 = sc[h][l][1], a2 = sc[h][l][2];
            float m = fmaxf(a0, fmaxf(a1, a2));
            float e0 = expf(a0 - m), e1 = expf(a1 - m), e2 = expf(a2 - m);
            float inv = 1.f / (e0 + e1 + e2);
            e0 *= inv; e1 *= inv; e2 *= inv;
            float4 z;
            z.x = e0*x4[0].x + e1*x4[1].x + e2*x4[2].x;
            z.y = e0*x4[0].y + e1*x4[1].y + e2*x4[2].y;
            z.z = e0*x4[0].z + e1*x4[1].z + e2*x4[2].z;
            z.w = e0*x4[0].w + e1*x4[1].w + e2*x4[2].w;
            *(float4*)(g_z + (long)w*768 + l*256 + h*128 + lane*4) = z;
        }
}

/* ------------------------- residual + LN + mean (warp/row) -------------------- */
__global__ __launch_bounds__(256) void k_ln(const float* __restrict__ g,
                                            const float* __restrict__ bb,
                                            float* __restrict__ out) {
    int w = blockIdx.x*8 + (threadIdx.x >> 5);
    if (w >= NB) return;
    int lane = threadIdx.x & 31;
    int b = w / NN, row = w - b*NN;
    float4 g4 = *(const float4*)(g + lane*4);
    float4 b4 = *(const float4*)(bb + lane*4);
    float4 acc = make_float4(0.f, 0.f, 0.f, 0.f);
#pragma unroll
    for (int l = 0; l < 3; l++) {
        float4 v0 = *(const float4*)(g_of + ((long)w*3 + l)*DD + lane*4);
        float4 v1 = *(const float4*)(g_seq + ((long)w*3 + l)*DD + lane*4);
        float4 v = make_float4(v0.x+v1.x, v0.y+v1.y, v0.z+v1.z, v0.w+v1.w);
        float s  = wrsum(v.x + v.y + v.z + v.w);
        float s2 = wrsum(dot4(v, v));
        float mu  = s * (1.f/128.f);
        float var = s2 * (1.f/128.f) - mu*mu;
        float is = rsqrtf(var + 1e-6f);
        acc.x += g4.x*(v.x - mu)*is + b4.x;
        acc.y += g4.y*(v.y - mu)*is + b4.y;
        acc.z += g4.z*(v.z - mu)*is + b4.z;
        acc.w += g4.w*(v.w - mu)*is + b4.w;
    }
    float4 r = make_float4(acc.x*(1.f/3.f), acc.y*(1.f/3.f),
                           acc.z*(1.f/3.f), acc.w*(1.f/3.f));
    *(float4*)(out + (long)b*NN*256 + (long)row*256 + lane*4) = r;
}

/* ------------------------- HGC pieces (warp/row) ------------------------------ */
__global__ __launch_bounds__(256) void k_u0(const float* __restrict__ e0,
                                            const float* __restrict__ e1) {
    int w = blockIdx.x*8 + (threadIdx.x >> 5);
    if (w >= NB) return;
    int lane = threadIdx.x & 31;
    int b = w / NN, row = w - b*NN;
    float4 x = *(const float4*)((b ? e1 : e0) + (long)row*DD + lane*4);
    float s = wrsum(dot4(x, x));
    float n0 = fmaxf(sqrtf(s), 1e-15f);
    float ne = tanhf(n0);
    float pe = (ne > MAXN_) ? MAXN_/ne : 1.f;
    float np = fmaxf(ne*pe, 1e-15f);
    float c  = atanhf(fminf(np, 1.f - 1e-7f)) / np * (ne / n0) * pe;
    *(float4*)(g_u + (long)w*DD + lane*4) =
        make_float4(c*x.x, c*x.y, c*x.z, c*x.w);
}

__global__ __launch_bounds__(256) void k_hgc_bias(const float* __restrict__ T,
                                                  const float* __restrict__ bvec,
                                                  float* __restrict__ Y) {
    int w = blockIdx.x*8 + (threadIdx.x >> 5);
    if (w >= NB) return;
    int lane = threadIdx.x & 31;
    float4 t4 = *(const float4*)(T + (long)w*DD + lane*4);
    float4 b4 = *(const float4*)(bvec + lane*4);
    float s0 = wrsum(dot4(t4, t4));
    float s1 = wrsum(dot4(b4, b4));
    float s2 = wrsum(dot4(t4, b4));
    float nt = fmaxf(sqrtf(s0), 1e-15f);
    float et = tanhf(nt);
    float pt = (et > MAXN_) ? MAXN_/et : 1.f;
    float cm = (et/nt) * pt;
    float x2 = (et*pt) * (et*pt);
    float nb = fmaxf(sqrtf(s1), 1e-15f);
    float eb = tanhf(nb);
    float pb = (eb > MAXN_) ? MAXN_/eb : 1.f;
    float cb = (eb/nb) * pb;
    float y2 = (eb*pb) * (eb*pb);
    float xy = cm * cb * s2;
    float den = fmaxf(1.f + 2.f*xy + x2*y2, 1e-15f);
    float fA = (1.f + 2.f*xy + y2) * cm / den;
    float fB = (1.f - x2) * cb / den;
    float4 r = make_float4(fA*t4.x + fB*b4.x, fA*t4.y + fB*b4.y,
                           fA*t4.z + fB*b4.z, fA*t4.w + fB*b4.w);
    float s3 = wrsum(dot4(r, r));
    float nr = fmaxf(sqrtf(s3), 1e-15f);
    float pr = (nr > MAXN_) ? MAXN_/nr : 1.f;
    float np = fmaxf(nr*pr, 1e-15f);
    float c2 = atanhf(fminf(np, 1.f - 1e-7f)) / np * pr;
    *(float4*)(Y + (long)w*DD + lane*4) =
        make_float4(c2*r.x, c2*r.y, c2*r.z, c2*r.w);
}

/* final==0: write W buffer.  final==1: write out[(2+b)] with ent residual. ----- */
__global__ __launch_bounds__(256) void k_hgc_agg(const float* __restrict__ Y,
                                                 float* __restrict__ W,
                                                 const float* __restrict__ e0,
                                                 const float* __restrict__ e1,
                                                 float* __restrict__ out,
                                                 int final_) {
    int w = blockIdx.x*8 + (threadIdx.x >> 5);
    if (w >= NB) return;
    int lane = threadIdx.x & 31;
    int b = w / NN, row = w - b*NN;
    const int* cols = g_adj_cols + (long)w * MAXDEG;
    int deg = g_adj_deg[w];
    float4 acc = make_float4(0.f, 0.f, 0.f, 0.f);
    for (int j = 0; j < deg; j++) {
        int c = __ldg(&cols[j]);
        float4 v = *(const float4*)(Y + (long)(b*NN + c)*DD + lane*4);
        acc.x += v.x; acc.y += v.y; acc.z += v.z; acc.w += v.w;
    }
    float inv = 1.f / (float)deg;
    float4 z = make_float4(acc.x*inv, acc.y*inv, acc.z*inv, acc.w*inv);
    float4 rz = make_float4(fmaxf(z.x, 0.f), fmaxf(z.y, 0.f),
                            fmaxf(z.z, 0.f), fmaxf(z.w, 0.f));
    float s0 = wrsum(dot4(z, z));
    float s1 = wrsum(dot4(rz, rz));
    float nz = fmaxf(sqrtf(s0), 1e-15f);
    float e1v = tanhf(nz);
    float p1 = (e1v > MAXN_) ? MAXN_/e1v : 1.f;
    float cH = (e1v/nz) * p1;
    float nH = fmaxf(e1v*p1, 1e-15f);
    float cT = atanhf(fminf(nH, 1.f - 1e-7f)) / nH * cH;
    float nt2 = fmaxf(cT * sqrtf(s1), 1e-15f);
    float e2 = tanhf(nt2);
    float p2 = (e2 > MAXN_) ? MAXN_/e2 : 1.f;
    float hcoef = (e2/nt2) * p2 * cT;
    float nH2 = fmaxf(e2*p2, 1e-15f);
    float c2 = atanhf(fminf(nH2, 1.f - 1e-7f)) / nH2;
    float cc = c2 * hcoef;
    if (final_) {
        float4 e = *(const float4*)((b ? e1 : e0) + (long)row*DD + lane*4);
        *(float4*)(out + (long)(2+b)*NN*256 + (long)row*256 + lane*4) =
            make_float4(e.x + cc*rz.x, e.y + cc*rz.y, e.z + cc*rz.z, e.w + cc*rz.w);
    } else {
        *(float4*)(W + (long)w*DD + lane*4) =
            make_float4(cc*rz.x, cc*rz.y, cc*rz.z, cc*rz.w);
    }
}

/* ------------------------- host driver ----------------------------------------- */
extern "C" void kernel_launch(void* const* d_in, const int* in_sizes, int n_in,
                              void* d_out, int out_size) {
    const float* ent_sr    = (const float*)d_in[0];
    const float* ent_tg    = (const float*)d_in[1];
    const float* rel_sr    = (const float*)d_in[2];
    const float* rel_tg    = (const float*)d_in[3];
    const float* adj_sr    = (const float*)d_in[4];
    const float* adj_tg    = (const float*)d_in[5];
    const float* rel_adj_sr= (const float*)d_in[6];
    const float* rel_adj_tg= (const float*)d_in[7];
    const float* gat_W     = (const float*)d_in[8];
    const float* gat_a_src = (const float*)d_in[9];
    const float* gat_a_dst = (const float*)d_in[10];
    const float* Wq        = (const float*)d_in[11];
    const float* Wk        = (const float*)d_in[12];
    const float* Wv        = (const float*)d_in[13];
    const float* Wfc       = (const float*)d_in[14];
    const float* ln_g      = (const float*)d_in[15];
    const float* ln_b      = (const float*)d_in[16];
    const float* hgc_W     = (const float*)d_in[17];
    const float* hgc_b     = (const float*)d_in[18];
    float* out = (float*)d_out;

    cudaFuncSetAttribute(k_hmma<128>, cudaFuncAttributeMaxDynamicSharedMemorySize, SMEM_128);
    cudaFuncSetAttribute(k_hmma<64>,  cudaFuncAttributeMaxDynamicSharedMemorySize, SMEM_64);

    float *seq, *mix, *mv, *y2, *z, *of, *u, *t, *y, *w, *Gt, *Pt, *Wgt;
    cudaGetSymbolAddress((void**)&seq, g_seq);
    cudaGetSymbolAddress((void**)&mix, g_mix);
    cudaGetSymbolAddress((void**)&mv,  g_mv);
    cudaGetSymbolAddress((void**)&y2,  g_y2);
    cudaGetSymbolAddress((void**)&z,   g_z);
    cudaGetSymbolAddress((void**)&of,  g_of);
    cudaGetSymbolAddress((void**)&u,   g_u);
    cudaGetSymbolAddress((void**)&t,   g_t);
    cudaGetSymbolAddress((void**)&y,   g_y);
    cudaGetSymbolAddress((void**)&w,   g_w);
    cudaGetSymbolAddress((void**)&Gt,  g_Gt);
    cudaGetSymbolAddress((void**)&Pt,  g_Pt);
    cudaGetSymbolAddress((void**)&Wgt, g_Wgt);

    dim3 gGAT(1, 188);     /* MT=64: [12000,256]@Wgt^T -> N=128 */
    dim3 gY  (2, 282);     /* MT=128 */
    dim3 gOF (1, 282);     /* MT=128 */
    dim3 gHGC(1, 188);     /* MT=64 */

    /* sparsify + precompute */
    k_build_adj<<<dim3(NN, 2), 256>>>(adj_sr, adj_tg);
    k_build_rel<<<dim3(NN, 2), 256>>>(rel_adj_sr, rel_adj_tg);
    k_relagg<<<NWB, 256>>>(rel_sr, rel_tg, out);
    k_precomp_Gt<<<256, 128>>>(Wq, Wk);
    k_precomp_Pt<<<256, 128>>>(Wv, Wfc);
    k_precomp_gat<<<8, 128>>>(gat_W, gat_a_src, gat_a_dst);
    k_precomp_Wgt<<<256, 256>>>(gat_W);
    k_seq0e<<<NWB, 256>>>(ent_sr, ent_tg);     /* copy + esed layer0 */

    /* GAT x2 */
    for (int L = 0; L < 2; L++) {
        k_gat_mix<<<NWB, 256>>>(L);
        k_hmma<64><<<gGAT, 256, SMEM_64>>>(mix, 256, Wgt + (long)L*128*256, 256,
                                           mv, 128, 12000, 256);
        k_gat_post<<<NWB, 256>>>(L + 1, L == 0 ? 1 : 0);
    }

    /* MHA */
    k_hmma<128><<<gY, 256, SMEM_128>>>(seq, 128, Gt, 128, y2, 256, 36000, 128);
    k_mha<<<NWB, 256>>>();
    k_hmma<128><<<gOF, 256, SMEM_128>>>(z, 256, Pt, 256, of, 128, 36000, 256);
    k_ln<<<NWB, 256>>>(ln_g, ln_b, out);

    /* HGC encoder */
    k_u0<<<NWB, 256>>>(ent_sr, ent_tg);
    k_hmma<64><<<gHGC, 256, SMEM_64>>>(u, 128, hgc_W, 128, t, 128, 12000, 128);
    k_hgc_bias<<<NWB, 256>>>(t, hgc_b, y);
    k_hgc_agg<<<NWB, 256>>>(y, w, ent_sr, ent_tg, out, 0);
    k_hmma<64><<<gHGC, 256, SMEM_64>>>(w, 128, hgc_W + DD*DD, 128, t, 128, 12000, 128);
    k_hgc_bias<<<NWB, 256>>>(t, hgc_b + DD, y);
    k_hgc_agg<<<NWB, 256>>>(y, w, ent_sr, ent_tg, out, 1);
}

// round 10
// speedup vs baseline: 1.4156x; 1.4156x over previous
#include <cuda_runtime.h>
#include <cuda_bf16.h>
#include <math.h>
#include <stdint.h>

#define NN      6000
#define DD      128
#define RR      1000
#define MAXDEG  128
#define MAXRDEG 64
#define NB      12000     /* 2*NN: both branches stacked */
#define NWB     1500      /* NB/8 warp-per-row grid */
#define MAXN_   0.996f    /* 1 - 4e-3 */

/* ------------------------- static scratch (no allocs) ------------------------- */
__device__ __align__(16) float g_seq[(long)NB*3*DD];       /* [n][l][d] */
__device__ __align__(16) float g_mix[(long)NB*2*DD];       /* [n][h*128+d] x-space mixed */
__device__ __align__(16) float g_mv [(long)NB*DD];         /* GAT layer pre-activation */
__device__ float g_es0[NB], g_ed0[NB], g_es1[NB], g_ed1[NB];
__device__ __align__(16) float g_y2[(long)NB*3*2*DD];      /* y = x @ G */
__device__ __align__(16) float g_z [(long)NB*3*2*DD];      /* attn-mixed x, per head */
__device__ __align__(16) float g_of[(long)NB*3*DD];
__device__ __align__(16) float g_u [(long)NB*DD];
__device__ __align__(16) float g_t [(long)NB*DD];
__device__ __align__(16) float g_y [(long)NB*DD];
__device__ __align__(16) float g_w [(long)NB*DD];
__device__ __align__(16) float g_Gt [2*DD*DD];             /* [t=h*128+d2][d1] */
__device__ __align__(16) float g_Pt [DD*2*DD];             /* [d2][hd] */
__device__ __align__(16) float g_Wgt[2*DD*2*DD];           /* [L][e][h*128+d] */
__device__ __align__(16) float g_wsd[2*2*2*DD];            /* [L][s][h][d] */
__device__ int g_adj_cols[(long)NB*MAXDEG];
__device__ int g_adj_deg[NB];
__device__ int g_rel_cols[(long)NB*MAXRDEG];
__device__ int g_rel_deg[NB];

/* ------------------------- warp helpers --------------------------------------- */
__device__ __forceinline__ float wrsum(float x) {
#pragma unroll
    for (int o = 16; o; o >>= 1) x += __shfl_xor_sync(0xffffffffu, x, o);
    return x;
}
__device__ __forceinline__ float wrmax(float x) {
#pragma unroll
    for (int o = 16; o; o >>= 1) x = fmaxf(x, __shfl_xor_sync(0xffffffffu, x, o));
    return x;
}
__device__ __forceinline__ float dot4(float4 a, float4 b) {
    return a.x*b.x + a.y*b.y + a.z*b.z + a.w*b.w;
}

/* ------------------------- CSR builders --------------------------------------- */
__global__ void k_build_adj(const float* __restrict__ a0, const float* __restrict__ a1) {
    int row = blockIdx.x, b = blockIdx.y;
    const float4* adj = (const float4*)((b ? a1 : a0) + (long)row * NN);
    __shared__ int cnt;
    if (threadIdx.x == 0) cnt = 0;
    __syncthreads();
    int* mc = g_adj_cols + (long)(b*NN + row) * MAXDEG;
    for (int c = threadIdx.x; c < NN/4; c += blockDim.x) {
        float4 v = adj[c];
        if (v.x > 0.f) { int p = atomicAdd(&cnt, 1); if (p < MAXDEG) mc[p] = c*4;   }
        if (v.y > 0.f) { int p = atomicAdd(&cnt, 1); if (p < MAXDEG) mc[p] = c*4+1; }
        if (v.z > 0.f) { int p = atomicAdd(&cnt, 1); if (p < MAXDEG) mc[p] = c*4+2; }
        if (v.w > 0.f) { int p = atomicAdd(&cnt, 1); if (p < MAXDEG) mc[p] = c*4+3; }
    }
    __syncthreads();
    if (threadIdx.x == 0) g_adj_deg[b*NN + row] = min(cnt, MAXDEG);
}
__global__ void k_build_rel(const float* __restrict__ a0, const float* __restrict__ a1) {
    int row = blockIdx.x, b = blockIdx.y;
    const float4* adj = (const float4*)((b ? a1 : a0) + (long)row * RR);
    __shared__ int cnt;
    if (threadIdx.x == 0) cnt = 0;
    __syncthreads();
    int* mc = g_rel_cols + (long)(b*NN + row) * MAXRDEG;
    for (int c = threadIdx.x; c < RR/4; c += blockDim.x) {
        float4 v = adj[c];
        if (v.x > 0.f) { int p = atomicAdd(&cnt, 1); if (p < MAXRDEG) mc[p] = c*4;   }
        if (v.y > 0.f) { int p = atomicAdd(&cnt, 1); if (p < MAXRDEG) mc[p] = c*4+1; }
        if (v.z > 0.f) { int p = atomicAdd(&cnt, 1); if (p < MAXRDEG) mc[p] = c*4+2; }
        if (v.w > 0.f) { int p = atomicAdd(&cnt, 1); if (p < MAXRDEG) mc[p] = c*4+3; }
    }
    __syncthreads();
    if (threadIdx.x == 0) g_rel_deg[b*NN + row] = min(cnt, MAXRDEG);
}

/* ------------------------- rel aggregator (warp/row) -------------------------- */
__global__ __launch_bounds__(256) void k_relagg(const float* __restrict__ r0,
                                                const float* __restrict__ r1,
                                                float* __restrict__ out) {
    int w = blockIdx.x*8 + (threadIdx.x >> 5);
    if (w >= NB) return;
    int lane = threadIdx.x & 31;
    int b = w / NN, row = w - b*NN;
    const float* remb = b ? r1 : r0;
    const int* cols = g_rel_cols + (long)w * MAXRDEG;
    int deg = g_rel_deg[w];
    float4 acc = make_float4(0.f, 0.f, 0.f, 0.f);
    for (int j = 0; j < deg; j++) {
        int c = __ldg(&cols[j]);
        float4 v = *(const float4*)(remb + (long)c*DD + lane*4);
        acc.x += v.x; acc.y += v.y; acc.z += v.z; acc.w += v.w;
    }
    float inv = 1.f / (float)deg;
    float4 r = make_float4(acc.x*inv, acc.y*inv, acc.z*inv, acc.w*inv);
    *(float4*)(out + (long)b*NN*256 + (long)row*256 + 128 + lane*4) = r;
    *(float4*)(out + (long)(2+b)*NN*256 + (long)row*256 + 128 + lane*4) = r;
}

/* ------------------------- seq slot-0 copy + esed(layer0) --------------------- */
__global__ __launch_bounds__(256) void k_seq0e(const float* __restrict__ e0,
                                               const float* __restrict__ e1) {
    int w = blockIdx.x*8 + (threadIdx.x >> 5);
    if (w >= NB) return;
    int lane = threadIdx.x & 31;
    int b = w / NN, row = w - b*NN;
    float4 x4 = *(const float4*)((b ? e1 : e0) + (long)row*DD + lane*4);
    *(float4*)(g_seq + (long)w*384 + lane*4) = x4;
    float4 ws0 = *(const float4*)(g_wsd       + lane*4);
    float4 ws1 = *(const float4*)(g_wsd + 128 + lane*4);
    float4 wd0 = *(const float4*)(g_wsd + 256 + lane*4);
    float4 wd1 = *(const float4*)(g_wsd + 384 + lane*4);
    float v0 = wrsum(dot4(x4, ws0));
    float v1 = wrsum(dot4(x4, wd0));
    float v2 = wrsum(dot4(x4, ws1));
    float v3 = wrsum(dot4(x4, wd1));
    if (lane == 0) { g_es0[w] = v0; g_ed0[w] = v1; g_es1[w] = v2; g_ed1[w] = v3; }
}

/* ------------------------- precompute: gat attn vectors + Wgt ----------------- */
__global__ void k_precomp_gat(const float* __restrict__ W, const float* __restrict__ asrc,
                              const float* __restrict__ adst) {
    int bi = blockIdx.x, d = threadIdx.x;           /* bi = L*4 + s*2 + h */
    int L = bi >> 2, s = (bi >> 1) & 1, h = bi & 1;
    const float* a = (s ? adst : asrc) + (L*2 + h)*128;
    const float* wr = W + (long)((L*2 + h)*128 + d)*128;
    float acc = 0.f;
    for (int e = 0; e < 128; e++) acc += wr[e] * a[e];
    g_wsd[bi*128 + d] = acc;
}
__global__ void k_precomp_Wgt(const float* __restrict__ W) {
    int idx = blockIdx.x*256 + threadIdx.x;        /* 2*2*128*128 */
    if (idx >= 2*2*DD*DD) return;
    int e = idx & 127, d = (idx >> 7) & 127, h = (idx >> 14) & 1, L = idx >> 15;
    g_Wgt[((long)L*128 + e)*256 + h*128 + d] = W[idx];
}

/* ------------------------- fused Gt/Pt precompute (4 small GEMMs) -------------
   blockIdx.x: 0,1 -> Gt_h  (C=Gt+h*16384, A=Wk+h*128 [m][k] lda256,
                             B=Wq+h*128 [n][k] ldb256, ldc=128)
               2,3 -> Pt_h  (C=Pt+h*128 ldc=256, A=Wfc+h*16384 [k][m] lda128,
                             B=Wv+h*128 [n][k] ldb256)                      ---- */
__global__ __launch_bounds__(256) void k_pre4(const float* __restrict__ Wq,
                                              const float* __restrict__ Wk,
                                              const float* __restrict__ Wv,
                                              const float* __restrict__ Wfc) {
    __shared__ float As[16][132];
    __shared__ float Bs[16][132];
    int id = blockIdx.x;
    int h = id & 1, which = id >> 1;
    const float *Ap, *Bp;
    float* Cp;
    int lda, amode, ldc;
    if (which == 0) {
        Ap = Wk + h*128;      lda = 256; amode = 0;
        Bp = Wq + h*128;
        Cp = g_Gt + h*128*128; ldc = 128;
    } else {
        Ap = Wfc + h*128*128; lda = 128; amode = 1;
        Bp = Wv + h*128;
        Cp = g_Pt + h*128;    ldc = 256;
    }
    int tid = threadIdx.x;
    int tx = tid & 15, ty = tid >> 4;
    float acc[8][8];
#pragma unroll
    for (int i = 0; i < 8; i++)
#pragma unroll
        for (int j = 0; j < 8; j++) acc[i][j] = 0.f;

    for (int k0 = 0; k0 < 128; k0 += 16) {
        if (amode == 0) {   /* A global [m][k] -> As[k][m] */
#pragma unroll
            for (int i = 0; i < 2; i++) {
                int lin = tid + i*256;
                int r = lin >> 2, c = (lin & 3) << 2;
                float4 av = *(const float4*)(Ap + (long)r*lda + k0 + c);
                As[c][r]=av.x; As[c+1][r]=av.y; As[c+2][r]=av.z; As[c+3][r]=av.w;
            }
        } else {            /* A global [k][m] -> As[k][m] direct */
#pragma unroll
            for (int i = 0; i < 2; i++) {
                int lin = tid + i*256;
                int r = lin >> 5, c = (lin & 31) << 2;
                *(float4*)&As[r][c] = *(const float4*)(Ap + (long)(k0+r)*lda + c);
            }
        }
        /* B global [n][k] (ldb 256) -> Bs[k][n] */
#pragma unroll
        for (int i = 0; i < 2; i++) {
            int lin = tid + i*256;
            int n = lin >> 2, c = (lin & 3) << 2;
            float4 bv = *(const float4*)(Bp + (long)n*256 + k0 + c);
            Bs[c][n]=bv.x; Bs[c+1][n]=bv.y; Bs[c+2][n]=bv.z; Bs[c+3][n]=bv.w;
        }
        __syncthreads();
#pragma unroll
        for (int kk = 0; kk < 16; kk++) {
            float a[8], bb[8];
            *(float4*)&a[0]  = *(const float4*)&As[kk][ty*8];
            *(float4*)&a[4]  = *(const float4*)&As[kk][ty*8 + 4];
            *(float4*)&bb[0] = *(const float4*)&Bs[kk][tx*8];
            *(float4*)&bb[4] = *(const float4*)&Bs[kk][tx*8 + 4];
#pragma unroll
            for (int i = 0; i < 8; i++)
#pragma unroll
                for (int j = 0; j < 8; j++) acc[i][j] += a[i] * bb[j];
        }
        __syncthreads();
    }
#pragma unroll
    for (int i = 0; i < 8; i++) {
        int r = ty*8 + i;
#pragma unroll
        for (int j = 0; j < 8; j += 4) {
            float4 cv = make_float4(acc[i][j], acc[i][j+1], acc[i][j+2], acc[i][j+3]);
            *(float4*)(Cp + (long)r*ldc + tx*8 + j) = cv;
        }
    }
}

/* ------------------------- bf16-split HMMA GEMM (R8-proven) ------------------- */
#define SLDA 40   /* smem row stride in halfs (32 + 8 pad) */

__device__ __forceinline__ void mma_bf16(float* d, const uint32_t* a,
                                         const uint32_t* b) {
    asm volatile(
        "mma.sync.aligned.m16n8k16.row.col.f32.bf16.bf16.f32 "
        "{%0,%1,%2,%3}, {%4,%5,%6,%7}, {%8,%9}, {%0,%1,%2,%3};"
        : "+f"(d[0]), "+f"(d[1]), "+f"(d[2]), "+f"(d[3])
        : "r"(a[0]), "r"(a[1]), "r"(a[2]), "r"(a[3]), "r"(b[0]), "r"(b[1]));
}

__global__ void __launch_bounds__(256, 1)
k_hmma(const float* __restrict__ A, int lda,
       const float* __restrict__ Bt, int ldb,
       float* __restrict__ C, int ldc, int M, int K) {
    __shared__ __nv_bfloat16 sAh[128*SLDA], sAl[128*SLDA];
    __shared__ __nv_bfloat16 sBh[128*SLDA], sBl[128*SLDA];
    int tid = threadIdx.x, wid = tid >> 5, lane = tid & 31;
    int wm = wid & 3, wn = wid >> 2;          /* 4 x 2 warp grid */
    int g = lane >> 2, tg = lane & 3;
    int bm = blockIdx.y * 128, bn = blockIdx.x * 128;

    float acc[2][8][4];
#pragma unroll
    for (int i = 0; i < 2; i++)
#pragma unroll
        for (int j = 0; j < 8; j++)
#pragma unroll
            for (int r = 0; r < 4; r++) acc[i][j][r] = 0.f;

    for (int kc = 0; kc < K; kc += 32) {
#pragma unroll
        for (int it = 0; it < 4; it++) {
            int idx = tid + it*256;            /* 1024 float4 slots */
            int r = idx >> 3, c4 = (idx & 7) << 2;
            float4 va = make_float4(0.f, 0.f, 0.f, 0.f);
            if (bm + r < M) va = *(const float4*)(A + (long)(bm+r)*lda + kc + c4);
            __nv_bfloat162 h0 = __float22bfloat162_rn(make_float2(va.x, va.y));
            __nv_bfloat162 h1 = __float22bfloat162_rn(make_float2(va.z, va.w));
            float2 f0 = __bfloat1622float2(h0), f1 = __bfloat1622float2(h1);
            __nv_bfloat162 l0 = __float22bfloat162_rn(make_float2(va.x-f0.x, va.y-f0.y));
            __nv_bfloat162 l1 = __float22bfloat162_rn(make_float2(va.z-f1.x, va.w-f1.y));
            *(uint2*)&sAh[r*SLDA + c4] = make_uint2(*(uint32_t*)&h0, *(uint32_t*)&h1);
            *(uint2*)&sAl[r*SLDA + c4] = make_uint2(*(uint32_t*)&l0, *(uint32_t*)&l1);

            float4 vb = *(const float4*)(Bt + (long)(bn+r)*ldb + kc + c4);
            h0 = __float22bfloat162_rn(make_float2(vb.x, vb.y));
            h1 = __float22bfloat162_rn(make_float2(vb.z, vb.w));
            f0 = __bfloat1622float2(h0); f1 = __bfloat1622float2(h1);
            l0 = __float22bfloat162_rn(make_float2(vb.x-f0.x, vb.y-f0.y));
            l1 = __float22bfloat162_rn(make_float2(vb.z-f1.x, vb.w-f1.y));
            *(uint2*)&sBh[r*SLDA + c4] = make_uint2(*(uint32_t*)&h0, *(uint32_t*)&h1);
            *(uint2*)&sBl[r*SLDA + c4] = make_uint2(*(uint32_t*)&l0, *(uint32_t*)&l1);
        }
        __syncthreads();

#pragma unroll
        for (int ks = 0; ks < 32; ks += 16) {
            uint32_t ah[2][4], al[2][4];
#pragma unroll
            for (int mt = 0; mt < 2; mt++) {
                int r0 = (wm*32 + mt*16 + g) * SLDA + ks + tg*2;
                int r8 = r0 + 8*SLDA;
                ah[mt][0] = *(const uint32_t*)&sAh[r0];
                ah[mt][1] = *(const uint32_t*)&sAh[r8];
                ah[mt][2] = *(const uint32_t*)&sAh[r0 + 8];
                ah[mt][3] = *(const uint32_t*)&sAh[r8 + 8];
                al[mt][0] = *(const uint32_t*)&sAl[r0];
                al[mt][1] = *(const uint32_t*)&sAl[r8];
                al[mt][2] = *(const uint32_t*)&sAl[r0 + 8];
                al[mt][3] = *(const uint32_t*)&sAl[r8 + 8];
            }
#pragma unroll
            for (int nt = 0; nt < 8; nt++) {
                int n0 = (wn*64 + nt*8 + g) * SLDA + ks + tg*2;
                uint32_t bh[2], bl[2];
                bh[0] = *(const uint32_t*)&sBh[n0];
                bh[1] = *(const uint32_t*)&sBh[n0 + 8];
                bl[0] = *(const uint32_t*)&sBl[n0];
                bl[1] = *(const uint32_t*)&sBl[n0 + 8];
                mma_bf16(acc[0][nt], ah[0], bh);
                mma_bf16(acc[1][nt], ah[1], bh);
                mma_bf16(acc[0][nt], ah[0], bl);
                mma_bf16(acc[1][nt], ah[1], bl);
                mma_bf16(acc[0][nt], al[0], bh);
                mma_bf16(acc[1][nt], al[1], bh);
            }
        }
        __syncthreads();
    }

#pragma unroll
    for (int mt = 0; mt < 2; mt++) {
        int r0 = bm + wm*32 + mt*16 + g;
#pragma unroll
        for (int nt = 0; nt < 8; nt++) {
            int c0 = bn + wn*64 + nt*8 + tg*2;
            if (r0 < M)
                *(float2*)(C + (long)r0*ldc + c0) =
                    make_float2(acc[mt][nt][0], acc[mt][nt][1]);
            if (r0 + 8 < M)
                *(float2*)(C + (long)(r0+8)*ldc + c0) =
                    make_float2(acc[mt][nt][2], acc[mt][nt][3]);
        }
    }
}

/* ------------------------- GAT: softmax-mix in x-space (warp/row) ------------- */
__global__ __launch_bounds__(256) void k_gat_mix(int L) {
    int w = blockIdx.x*8 + (threadIdx.x >> 5);
    if (w >= NB) return;
    int lane = threadIdx.x & 31;
    int b = w / NN;
    int deg = g_adj_deg[w];
    const int* cols = g_adj_cols + (long)w * MAXDEG;
    int creg[4]; float e0r[4], e1r[4];
    float es0 = g_es0[w], es1 = g_es1[w];
    float m0 = -1e30f, m1 = -1e30f;
#pragma unroll
    for (int i = 0; i < 4; i++) {
        int j = i*32 + lane;
        creg[i] = 0; e0r[i] = -1e30f; e1r[i] = -1e30f;
        if (j < deg) {
            int c = cols[j]; creg[i] = c;
            float t0 = es0 + g_ed0[b*NN + c]; e0r[i] = (t0 > 0.f) ? t0 : 0.2f*t0;
            float t1 = es1 + g_ed1[b*NN + c]; e1r[i] = (t1 > 0.f) ? t1 : 0.2f*t1;
            m0 = fmaxf(m0, e0r[i]); m1 = fmaxf(m1, e1r[i]);
        }
    }
    m0 = wrmax(m0); m1 = wrmax(m1);
    float s0 = 0.f, s1 = 0.f;
    float p0r[4], p1r[4];
#pragma unroll
    for (int i = 0; i < 4; i++) {
        int j = i*32 + lane;
        p0r[i] = (j < deg) ? expf(e0r[i] - m0) : 0.f;
        p1r[i] = (j < deg) ? expf(e1r[i] - m1) : 0.f;
        s0 += p0r[i]; s1 += p1r[i];
    }
    s0 = wrsum(s0); s1 = wrsum(s1);
    float inv0 = 0.5f / s0, inv1 = 0.5f / s1;   /* fold head-mean */
    float4 a0 = make_float4(0.f, 0.f, 0.f, 0.f);
    float4 a1 = make_float4(0.f, 0.f, 0.f, 0.f);
    for (int i = 0; i < 4 && i*32 < deg; i++) {
        for (int l = 0; l < 32; l++) {
            int j = i*32 + l;
            if (j >= deg) break;                    /* uniform across warp */
            int   c  = __shfl_sync(0xffffffffu, creg[i], l);
            float w0 = __shfl_sync(0xffffffffu, p0r[i], l) * inv0;
            float w1 = __shfl_sync(0xffffffffu, p1r[i], l) * inv1;
            float4 x4 = *(const float4*)(g_seq + (long)(b*NN + c)*384 + L*128 + lane*4);
            a0.x += w0*x4.x; a0.y += w0*x4.y; a0.z += w0*x4.z; a0.w += w0*x4.w;
            a1.x += w1*x4.x; a1.y += w1*x4.y; a1.z += w1*x4.z; a1.w += w1*x4.w;
        }
    }
    *(float4*)(g_mix + (long)w*256       + lane*4) = a0;
    *(float4*)(g_mix + (long)w*256 + 128 + lane*4) = a1;
}

/* ------------------ GAT: elu + normalize -> seq slot (+ esed layer1) ---------- */
__global__ __launch_bounds__(256) void k_gat_post(int lslot, int doEsed) {
    int w = blockIdx.x*8 + (threadIdx.x >> 5);
    if (w >= NB) return;
    int lane = threadIdx.x & 31;
    float4 mv = *(const float4*)(g_mv + (long)w*DD + lane*4);
    float4 ev;
    ev.x = (mv.x > 0.f) ? mv.x : expm1f(mv.x);
    ev.y = (mv.y > 0.f) ? mv.y : expm1f(mv.y);
    ev.z = (mv.z > 0.f) ? mv.z : expm1f(mv.z);
    ev.w = (mv.w > 0.f) ? mv.w : expm1f(mv.w);
    float ss = wrsum(dot4(ev, ev));
    float nrm = 1.f / fmaxf(sqrtf(ss), 1e-12f);
    float4 r = make_float4(ev.x*nrm, ev.y*nrm, ev.z*nrm, ev.w*nrm);
    *(float4*)(g_seq + ((long)w*3 + lslot)*DD + lane*4) = r;
    if (doEsed) {
        const float* base = g_wsd + 512;       /* layer-1 vectors */
        float4 ws0 = *(const float4*)(base       + lane*4);
        float4 ws1 = *(const float4*)(base + 128 + lane*4);
        float4 wd0 = *(const float4*)(base + 256 + lane*4);
        float4 wd1 = *(const float4*)(base + 384 + lane*4);
        float v0 = wrsum(dot4(r, ws0));
        float v1 = wrsum(dot4(r, wd0));
        float v2 = wrsum(dot4(r, ws1));
        float v3 = wrsum(dot4(r, wd1));
        if (lane == 0) { g_es0[w] = v0; g_ed0[w] = v1; g_es1[w] = v2; g_ed1[w] = v3; }
    }
}

/* ------------------------- MHA: scores via y.x, mix x (warp/node) ------------- */
__global__ __launch_bounds__(256) void k_mha() {
    int w = blockIdx.x*8 + (threadIdx.x >> 5);
    if (w >= NB) return;
    int lane = threadIdx.x & 31;
    float4 x4[3], y4[3][2];
#pragma unroll
    for (int l = 0; l < 3; l++) {
        x4[l] = *(const float4*)(g_seq + (long)w*384 + l*128 + lane*4);
#pragma unroll
        for (int h = 0; h < 2; h++)
            y4[l][h] = *(const float4*)(g_y2 + (long)w*768 + l*256 + h*128 + lane*4);
    }
    float sc[2][3][3];
#pragma unroll
    for (int h = 0; h < 2; h++)
#pragma unroll
        for (int l = 0; l < 3; l++)
#pragma unroll
            for (int m = 0; m < 3; m++)
                sc[h][l][m] = wrsum(dot4(y4[l][h], x4[m])) * 0.08838834764831845f;
#pragma unroll
    for (int h = 0; h < 2; h++)
#pragma unroll
        for (int l = 0; l < 3; l++) {
            float a0 = sc[h][l][0], a1 = sc[h][l][1], a2 = sc[h][l][2];
            float m = fmaxf(a0, fmaxf(a1, a2));
            float e0 = expf(a0 - m), e1 = expf(a1 - m), e2 = expf(a2 - m);
            float inv = 1.f / (e0 + e1 + e2);
            e0 *= inv; e1 *= inv; e2 *= inv;
            float4 z;
            z.x = e0*x4[0].x + e1*x4[1].x + e2*x4[2].x;
            z.y = e0*x4[0].y + e1*x4[1].y + e2*x4[2].y;
            z.z = e0*x4[0].z + e1*x4[1].z + e2*x4[2].z;
            z.w = e0*x4[0].w + e1*x4[1].w + e2*x4[2].w;
            *(float4*)(g_z + (long)w*768 + l*256 + h*128 + lane*4) = z;
        }
}

/* ------------------------- residual + LN + mean (warp/row) -------------------- */
__global__ __launch_bounds__(256) void k_ln(const float* __restrict__ g,
                                            const float* __restrict__ bb,
                                            float* __restrict__ out) {
    int w = blockIdx.x*8 + (threadIdx.x >> 5);
    if (w >= NB) return;
    int lane = threadIdx.x & 31;
    int b = w / NN, row = w - b*NN;
    float4 g4 = *(const float4*)(g + lane*4);
    float4 b4 = *(const float4*)(bb + lane*4);
    float4 acc = make_float4(0.f, 0.f, 0.f, 0.f);
#pragma unroll
    for (int l = 0; l < 3; l++) {
        float4 v0 = *(const float4*)(g_of + ((long)w*3 + l)*DD + lane*4);
        float4 v1 = *(const float4*)(g_seq + ((long)w*3 + l)*DD + lane*4);
        float4 v = make_float4(v0.x+v1.x, v0.y+v1.y, v0.z+v1.z, v0.w+v1.w);
        float s  = wrsum(v.x + v.y + v.z + v.w);
        float s2 = wrsum(dot4(v, v));
        float mu  = s * (1.f/128.f);
        float var = s2 * (1.f/128.f) - mu*mu;
        float is = rsqrtf(var + 1e-6f);
        acc.x += g4.x*(v.x - mu)*is + b4.x;
        acc.y += g4.y*(v.y - mu)*is + b4.y;
        acc.z += g4.z*(v.z - mu)*is + b4.z;
        acc.w += g4.w*(v.w - mu)*is + b4.w;
    }
    float4 r = make_float4(acc.x*(1.f/3.f), acc.y*(1.f/3.f),
                           acc.z*(1.f/3.f), acc.w*(1.f/3.f));
    *(float4*)(out + (long)b*NN*256 + (long)row*256 + lane*4) = r;
}

/* ------------------------- HGC pieces (warp/row) ------------------------------ */
__global__ __launch_bounds__(256) void k_u0(const float* __restrict__ e0,
                                            const float* __restrict__ e1) {
    int w = blockIdx.x*8 + (threadIdx.x >> 5);
    if (w >= NB) return;
    int lane = threadIdx.x & 31;
    int b = w / NN, row = w - b*NN;
    float4 x = *(const float4*)((b ? e1 : e0) + (long)row*DD + lane*4);
    float s = wrsum(dot4(x, x));
    float n0 = fmaxf(sqrtf(s), 1e-15f);
    float ne = tanhf(n0);
    float pe = (ne > MAXN_) ? MAXN_/ne : 1.f;
    float np = fmaxf(ne*pe, 1e-15f);
    float c  = atanhf(fminf(np, 1.f - 1e-7f)) / np * (ne / n0) * pe;
    *(float4*)(g_u + (long)w*DD + lane*4) =
        make_float4(c*x.x, c*x.y, c*x.z, c*x.w);
}

__global__ __launch_bounds__(256) void k_hgc_bias(const float* __restrict__ T,
                                                  const float* __restrict__ bvec,
                                                  float* __restrict__ Y) {
    int w = blockIdx.x*8 + (threadIdx.x >> 5);
    if (w >= NB) return;
    int lane = threadIdx.x & 31;
    float4 t4 = *(const float4*)(T + (long)w*DD + lane*4);
    float4 b4 = *(const float4*)(bvec + lane*4);
    float s0 = wrsum(dot4(t4, t4));
    float s1 = wrsum(dot4(b4, b4));
    float s2 = wrsum(dot4(t4, b4));
    float nt = fmaxf(sqrtf(s0), 1e-15f);
    float et = tanhf(nt);
    float pt = (et > MAXN_) ? MAXN_/et : 1.f;
    float cm = (et/nt) * pt;
    float x2 = (et*pt) * (et*pt);
    float nb = fmaxf(sqrtf(s1), 1e-15f);
    float eb = tanhf(nb);
    float pb = (eb > MAXN_) ? MAXN_/eb : 1.f;
    float cb = (eb/nb) * pb;
    float y2 = (eb*pb) * (eb*pb);
    float xy = cm * cb * s2;
    float den = fmaxf(1.f + 2.f*xy + x2*y2, 1e-15f);
    float fA = (1.f + 2.f*xy + y2) * cm / den;
    float fB = (1.f - x2) * cb / den;
    float4 r = make_float4(fA*t4.x + fB*b4.x, fA*t4.y + fB*b4.y,
                           fA*t4.z + fB*b4.z, fA*t4.w + fB*b4.w);
    float s3 = wrsum(dot4(r, r));
    float nr = fmaxf(sqrtf(s3), 1e-15f);
    float pr = (nr > MAXN_) ? MAXN_/nr : 1.f;
    float np = fmaxf(nr*pr, 1e-15f);
    float c2 = atanhf(fminf(np, 1.f - 1e-7f)) / np * pr;
    *(float4*)(Y + (long)w*DD + lane*4) =
        make_float4(c2*r.x, c2*r.y, c2*r.z, c2*r.w);
}

/* final==0: write W buffer.  final==1: write out[(2+b)] with ent residual. ----- */
__global__ __launch_bounds__(256) void k_hgc_agg(const float* __restrict__ Y,
                                                 float* __restrict__ W,
                                                 const float* __restrict__ e0,
                                                 const float* __restrict__ e1,
                                                 float* __restrict__ out,
                                                 int final_) {
    int w = blockIdx.x*8 + (threadIdx.x >> 5);
    if (w >= NB) return;
    int lane = threadIdx.x & 31;
    int b = w / NN, row = w - b*NN;
    const int* cols = g_adj_cols + (long)w * MAXDEG;
    int deg = g_adj_deg[w];
    float4 acc = make_float4(0.f, 0.f, 0.f, 0.f);
    for (int j = 0; j < deg; j++) {
        int c = __ldg(&cols[j]);
        float4 v = *(const float4*)(Y + (long)(b*NN + c)*DD + lane*4);
        acc.x += v.x; acc.y += v.y; acc.z += v.z; acc.w += v.w;
    }
    float inv = 1.f / (float)deg;
    float4 z = make_float4(acc.x*inv, acc.y*inv, acc.z*inv, acc.w*inv);
    float4 rz = make_float4(fmaxf(z.x, 0.f), fmaxf(z.y, 0.f),
                            fmaxf(z.z, 0.f), fmaxf(z.w, 0.f));
    float s0 = wrsum(dot4(z, z));
    float s1 = wrsum(dot4(rz, rz));
    float nz = fmaxf(sqrtf(s0), 1e-15f);
    float e1v = tanhf(nz);
    float p1 = (e1v > MAXN_) ? MAXN_/e1v : 1.f;
    float cH = (e1v/nz) * p1;
    float nH = fmaxf(e1v*p1, 1e-15f);
    float cT = atanhf(fminf(nH, 1.f - 1e-7f)) / nH * cH;
    float nt2 = fmaxf(cT * sqrtf(s1), 1e-15f);
    float e2 = tanhf(nt2);
    float p2 = (e2 > MAXN_) ? MAXN_/e2 : 1.f;
    float hcoef = (e2/nt2) * p2 * cT;
    float nH2 = fmaxf(e2*p2, 1e-15f);
    float c2 = atanhf(fminf(nH2, 1.f - 1e-7f)) / nH2;
    float cc = c2 * hcoef;
    if (final_) {
        float4 e = *(const float4*)((b ? e1 : e0) + (long)row*DD + lane*4);
        *(float4*)(out + (long)(2+b)*NN*256 + (long)row*256 + lane*4) =
            make_float4(e.x + cc*rz.x, e.y + cc*rz.y, e.z + cc*rz.z, e.w + cc*rz.w);
    } else {
        *(float4*)(W + (long)w*DD + lane*4) =
            make_float4(cc*rz.x, cc*rz.y, cc*rz.z, cc*rz.w);
    }
}

/* ------------------------- host driver ----------------------------------------- */
extern "C" void kernel_launch(void* const* d_in, const int* in_sizes, int n_in,
                              void* d_out, int out_size) {
    const float* ent_sr    = (const float*)d_in[0];
    const float* ent_tg    = (const float*)d_in[1];
    const float* rel_sr    = (const float*)d_in[2];
    const float* rel_tg    = (const float*)d_in[3];
    const float* adj_sr    = (const float*)d_in[4];
    const float* adj_tg    = (const float*)d_in[5];
    const float* rel_adj_sr= (const float*)d_in[6];
    const float* rel_adj_tg= (const float*)d_in[7];
    const float* gat_W     = (const float*)d_in[8];
    const float* gat_a_src = (const float*)d_in[9];
    const float* gat_a_dst = (const float*)d_in[10];
    const float* Wq        = (const float*)d_in[11];
    const float* Wk        = (const float*)d_in[12];
    const float* Wv        = (const float*)d_in[13];
    const float* Wfc       = (const float*)d_in[14];
    const float* ln_g      = (const float*)d_in[15];
    const float* ln_b      = (const float*)d_in[16];
    const float* hgc_W     = (const float*)d_in[17];
    const float* hgc_b     = (const float*)d_in[18];
    float* out = (float*)d_out;

    float *seq, *mix, *mv, *y2, *z, *of, *u, *t, *y, *w, *Gt, *Pt, *Wgt;
    cudaGetSymbolAddress((void**)&seq, g_seq);
    cudaGetSymbolAddress((void**)&mix, g_mix);
    cudaGetSymbolAddress((void**)&mv,  g_mv);
    cudaGetSymbolAddress((void**)&y2,  g_y2);
    cudaGetSymbolAddress((void**)&z,   g_z);
    cudaGetSymbolAddress((void**)&of,  g_of);
    cudaGetSymbolAddress((void**)&u,   g_u);
    cudaGetSymbolAddress((void**)&t,   g_t);
    cudaGetSymbolAddress((void**)&y,   g_y);
    cudaGetSymbolAddress((void**)&w,   g_w);
    cudaGetSymbolAddress((void**)&Gt,  g_Gt);
    cudaGetSymbolAddress((void**)&Pt,  g_Pt);
    cudaGetSymbolAddress((void**)&Wgt, g_Wgt);

    dim3 gGAT(1, 94);      /* [12000,256]@Wgt^T -> N=128 */
    dim3 gY  (2, 282);     /* [36000,128]@Gt^T  -> N=256 */
    dim3 gOF (1, 282);     /* [36000,256]@Pt^T  -> N=128 */
    dim3 gHGC(1, 94);

    /* sparsify + precompute */
    k_build_adj<<<dim3(NN, 2), 256>>>(adj_sr, adj_tg);
    k_build_rel<<<dim3(NN, 2), 256>>>(rel_adj_sr, rel_adj_tg);
    k_relagg<<<NWB, 256>>>(rel_sr, rel_tg, out);
    k_pre4<<<4, 256>>>(Wq, Wk, Wv, Wfc);
    k_precomp_gat<<<8, 128>>>(gat_W, gat_a_src, gat_a_dst);
    k_precomp_Wgt<<<256, 256>>>(gat_W);
    k_seq0e<<<NWB, 256>>>(ent_sr, ent_tg);     /* copy + esed layer0 */

    /* GAT x2 */
    for (int L = 0; L < 2; L++) {
        k_gat_mix<<<NWB, 256>>>(L);
        k_hmma<<<gGAT, 256>>>(mix, 256, Wgt + (long)L*128*256, 256,
                              mv, 128, 12000, 256);
        k_gat_post<<<NWB, 256>>>(L + 1, L == 0 ? 1 : 0);
    }

    /* MHA */
    k_hmma<<<gY, 256>>>(seq, 128, Gt, 128, y2, 256, 36000, 128);
    k_mha<<<NWB, 256>>>();
    k_hmma<<<gOF, 256>>>(z, 256, Pt, 256, of, 128, 36000, 256);
    k_ln<<<NWB, 256>>>(ln_g, ln_b, out);

    /* HGC encoder */
    k_u0<<<NWB, 256>>>(ent_sr, ent_tg);
    k_hmma<<<gHGC, 256>>>(u, 128, hgc_W, 128, t, 128, 12000, 128);
    k_hgc_bias<<<NWB, 256>>>(t, hgc_b, y);
    k_hgc_agg<<<NWB, 256>>>(y, w, ent_sr, ent_tg, out, 0);
    k_hmma<<<gHGC, 256>>>(w, 128, hgc_W + DD*DD, 128, t, 128, 12000, 128);
    k_hgc_bias<<<NWB, 256>>>(t, hgc_b + DD, y);
    k_hgc_agg<<<NWB, 256>>>(y, w, ent_sr, ent_tg, out, 1);
}

// round 11
// speedup vs baseline: 1.4635x; 1.0339x over previous
#include <cuda_runtime.h>
#include <cuda_bf16.h>
#include <math.h>
#include <stdint.h>

#define NN      6000
#define DD      128
#define RR      1000
#define MAXDEG  128
#define MAXRDEG 64
#define NB      12000     /* 2*NN: both branches stacked */
#define NWB     1500      /* NB/8 warp-per-row grid */
#define MAXN_   0.996f    /* 1 - 4e-3 */

/* ------------------------- static scratch (no allocs) ------------------------- */
__device__ __align__(16) float g_seq[(long)NB*3*DD];       /* [n][l][d] */
__device__ __align__(16) float g_mix[(long)NB*2*DD];       /* [n][h*128+d] x-space mixed */
__device__ __align__(16) float g_mv [(long)NB*DD];         /* GAT layer pre-activation */
__device__ float g_es0[NB], g_ed0[NB], g_es1[NB], g_ed1[NB];
__device__ __align__(16) float g_y2[(long)NB*3*2*DD];      /* y = x @ G */
__device__ __align__(16) float g_z [(long)NB*3*2*DD];      /* attn-mixed x, per head */
__device__ __align__(16) float g_of[(long)NB*3*DD];
__device__ __align__(16) float g_u [(long)NB*DD];
__device__ __align__(16) float g_t [(long)NB*DD];
__device__ __align__(16) float g_y [(long)NB*DD];
__device__ __align__(16) float g_w [(long)NB*DD];
__device__ __align__(16) float g_Gt [2*DD*DD];             /* [t=h*128+d2][d1] */
__device__ __align__(16) float g_Pt [DD*2*DD];             /* [d2][hd] */
__device__ __align__(16) float g_Wgt[2*DD*2*DD];           /* [L][e][h*128+d] */
__device__ __align__(16) float g_wsd[2*2*2*DD];            /* [L][s][h][d] */
__device__ int g_adj_cols[(long)NB*MAXDEG];
__device__ int g_adj_deg[NB];
__device__ int g_rel_cols[(long)NB*MAXRDEG];
__device__ int g_rel_deg[NB];

/* ------------------------- warp helpers --------------------------------------- */
__device__ __forceinline__ float wrsum(float x) {
#pragma unroll
    for (int o = 16; o; o >>= 1) x += __shfl_xor_sync(0xffffffffu, x, o);
    return x;
}
__device__ __forceinline__ float wrmax(float x) {
#pragma unroll
    for (int o = 16; o; o >>= 1) x = fmaxf(x, __shfl_xor_sync(0xffffffffu, x, o));
    return x;
}
__device__ __forceinline__ float dot4(float4 a, float4 b) {
    return a.x*b.x + a.y*b.y + a.z*b.z + a.w*b.w;
}

/* ------------------------- CSR builders --------------------------------------- */
__global__ void k_build_adj(const float* __restrict__ a0, const float* __restrict__ a1) {
    int row = blockIdx.x, b = blockIdx.y;
    const float4* adj = (const float4*)((b ? a1 : a0) + (long)row * NN);
    __shared__ int cnt;
    if (threadIdx.x == 0) cnt = 0;
    __syncthreads();
    int* mc = g_adj_cols + (long)(b*NN + row) * MAXDEG;
    for (int c = threadIdx.x; c < NN/4; c += blockDim.x) {
        float4 v = adj[c];
        if (v.x > 0.f) { int p = atomicAdd(&cnt, 1); if (p < MAXDEG) mc[p] = c*4;   }
        if (v.y > 0.f) { int p = atomicAdd(&cnt, 1); if (p < MAXDEG) mc[p] = c*4+1; }
        if (v.z > 0.f) { int p = atomicAdd(&cnt, 1); if (p < MAXDEG) mc[p] = c*4+2; }
        if (v.w > 0.f) { int p = atomicAdd(&cnt, 1); if (p < MAXDEG) mc[p] = c*4+3; }
    }
    __syncthreads();
    if (threadIdx.x == 0) g_adj_deg[b*NN + row] = min(cnt, MAXDEG);
}
__global__ void k_build_rel(const float* __restrict__ a0, const float* __restrict__ a1) {
    int row = blockIdx.x, b = blockIdx.y;
    const float4* adj = (const float4*)((b ? a1 : a0) + (long)row * RR);
    __shared__ int cnt;
    if (threadIdx.x == 0) cnt = 0;
    __syncthreads();
    int* mc = g_rel_cols + (long)(b*NN + row) * MAXRDEG;
    for (int c = threadIdx.x; c < RR/4; c += blockDim.x) {
        float4 v = adj[c];
        if (v.x > 0.f) { int p = atomicAdd(&cnt, 1); if (p < MAXRDEG) mc[p] = c*4;   }
        if (v.y > 0.f) { int p = atomicAdd(&cnt, 1); if (p < MAXRDEG) mc[p] = c*4+1; }
        if (v.z > 0.f) { int p = atomicAdd(&cnt, 1); if (p < MAXRDEG) mc[p] = c*4+2; }
        if (v.w > 0.f) { int p = atomicAdd(&cnt, 1); if (p < MAXRDEG) mc[p] = c*4+3; }
    }
    __syncthreads();
    if (threadIdx.x == 0) g_rel_deg[b*NN + row] = min(cnt, MAXRDEG);
}

/* ------------------------- rel aggregator (warp/row) -------------------------- */
__global__ __launch_bounds__(256) void k_relagg(const float* __restrict__ r0,
                                                const float* __restrict__ r1,
                                                float* __restrict__ out) {
    int w = blockIdx.x*8 + (threadIdx.x >> 5);
    if (w >= NB) return;
    int lane = threadIdx.x & 31;
    int b = w / NN, row = w - b*NN;
    const float* remb = b ? r1 : r0;
    const int* cols = g_rel_cols + (long)w * MAXRDEG;
    int deg = g_rel_deg[w];
    float4 acc = make_float4(0.f, 0.f, 0.f, 0.f);
    for (int j = 0; j < deg; j++) {
        int c = __ldg(&cols[j]);
        float4 v = *(const float4*)(remb + (long)c*DD + lane*4);
        acc.x += v.x; acc.y += v.y; acc.z += v.z; acc.w += v.w;
    }
    float inv = 1.f / (float)deg;
    float4 r = make_float4(acc.x*inv, acc.y*inv, acc.z*inv, acc.w*inv);
    *(float4*)(out + (long)b*NN*256 + (long)row*256 + 128 + lane*4) = r;
    *(float4*)(out + (long)(2+b)*NN*256 + (long)row*256 + 128 + lane*4) = r;
}

/* ------------- seq slot-0 copy + esed(layer0) + u0 (expmap0) ------------------ */
__global__ __launch_bounds__(256) void k_seq0e(const float* __restrict__ e0,
                                               const float* __restrict__ e1) {
    int w = blockIdx.x*8 + (threadIdx.x >> 5);
    if (w >= NB) return;
    int lane = threadIdx.x & 31;
    int b = w / NN, row = w - b*NN;
    float4 x4 = *(const float4*)((b ? e1 : e0) + (long)row*DD + lane*4);
    *(float4*)(g_seq + (long)w*384 + lane*4) = x4;
    float4 ws0 = *(const float4*)(g_wsd       + lane*4);
    float4 ws1 = *(const float4*)(g_wsd + 128 + lane*4);
    float4 wd0 = *(const float4*)(g_wsd + 256 + lane*4);
    float4 wd1 = *(const float4*)(g_wsd + 384 + lane*4);
    float v0 = wrsum(dot4(x4, ws0));
    float v1 = wrsum(dot4(x4, wd0));
    float v2 = wrsum(dot4(x4, ws1));
    float v3 = wrsum(dot4(x4, wd1));
    if (lane == 0) { g_es0[w] = v0; g_ed0[w] = v1; g_es1[w] = v2; g_ed1[w] = v3; }
    /* u0: expmap0(proj) coefficient */
    float s = wrsum(dot4(x4, x4));
    float n0 = fmaxf(sqrtf(s), 1e-15f);
    float ne = tanhf(n0);
    float pe = (ne > MAXN_) ? MAXN_/ne : 1.f;
    float np = fmaxf(ne*pe, 1e-15f);
    float c  = atanhf(fminf(np, 1.f - 1e-7f)) / np * (ne / n0) * pe;
    *(float4*)(g_u + (long)w*DD + lane*4) =
        make_float4(c*x4.x, c*x4.y, c*x4.z, c*x4.w);
}

/* ------------------------- precompute: gat attn vectors + Wgt ----------------- */
__global__ void k_precomp_gat(const float* __restrict__ W, const float* __restrict__ asrc,
                              const float* __restrict__ adst) {
    int bi = blockIdx.x, d = threadIdx.x;           /* bi = L*4 + s*2 + h */
    int L = bi >> 2, s = (bi >> 1) & 1, h = bi & 1;
    const float* a = (s ? adst : asrc) + (L*2 + h)*128;
    const float* wr = W + (long)((L*2 + h)*128 + d)*128;
    float acc = 0.f;
    for (int e = 0; e < 128; e++) acc += wr[e] * a[e];
    g_wsd[bi*128 + d] = acc;
}
__global__ void k_precomp_Wgt(const float* __restrict__ W) {
    int idx = blockIdx.x*256 + threadIdx.x;        /* 2*2*128*128 */
    if (idx >= 2*2*DD*DD) return;
    int e = idx & 127, d = (idx >> 7) & 127, h = (idx >> 14) & 1, L = idx >> 15;
    g_Wgt[((long)L*128 + e)*256 + h*128 + d] = W[idx];
}

/* ---------------- fused Gt/Pt precompute: 16 CTAs, 64x64 quadrants ------------
   gid = blockIdx.x>>2 : 0,1 -> Gt_h; 2,3 -> Pt_h.  quad = blockIdx.x&3.   ---- */
__global__ __launch_bounds__(256) void k_pre4(const float* __restrict__ Wq,
                                              const float* __restrict__ Wk,
                                              const float* __restrict__ Wv,
                                              const float* __restrict__ Wfc) {
    __shared__ float As[16][68];
    __shared__ float Bs[16][68];
    int gid = blockIdx.x >> 2, quad = blockIdx.x & 3;
    int h = gid & 1, which = gid >> 1;
    int m0 = (quad >> 1) * 64, n0 = (quad & 1) * 64;
    const float *Ap, *Bp;
    float* Cp;
    int lda, amode, ldc;
    if (which == 0) {
        Ap = Wk + h*128;       lda = 256; amode = 0;   /* A[m][k] */
        Bp = Wq + h*128;
        Cp = g_Gt + h*128*128; ldc = 128;
    } else {
        Ap = Wfc + h*128*128;  lda = 128; amode = 1;   /* A[k][m] */
        Bp = Wv + h*128;
        Cp = g_Pt + h*128;     ldc = 256;
    }
    int tid = threadIdx.x;
    int tx = tid & 15, ty = tid >> 4;
    float acc[4][4];
#pragma unroll
    for (int i = 0; i < 4; i++)
#pragma unroll
        for (int j = 0; j < 4; j++) acc[i][j] = 0.f;

    for (int k0 = 0; k0 < 128; k0 += 16) {
        if (amode == 0) {   /* A[m][k] -> As[k][m], m in [m0,m0+64) */
            int r = tid >> 2, c = (tid & 3) << 2;       /* 64 x 16 */
            float4 av = *(const float4*)(Ap + (long)(m0 + r)*lda + k0 + c);
            As[c][r]=av.x; As[c+1][r]=av.y; As[c+2][r]=av.z; As[c+3][r]=av.w;
        } else {            /* A[k][m] -> As[k][m] direct, 16 x 64 */
            int r = tid >> 4, c = (tid & 15) << 2;
            *(float4*)&As[r][c] = *(const float4*)(Ap + (long)(k0+r)*lda + m0 + c);
        }
        {                   /* B[n][k] (ldb 256) -> Bs[k][n], n in [n0,n0+64) */
            int n = tid >> 2, c = (tid & 3) << 2;
            float4 bv = *(const float4*)(Bp + (long)(n0 + n)*256 + k0 + c);
            Bs[c][n]=bv.x; Bs[c+1][n]=bv.y; Bs[c+2][n]=bv.z; Bs[c+3][n]=bv.w;
        }
        __syncthreads();
#pragma unroll
        for (int kk = 0; kk < 16; kk++) {
            float a[4], bb[4];
            *(float4*)&a[0]  = *(const float4*)&As[kk][ty*4];
            *(float4*)&bb[0] = *(const float4*)&Bs[kk][tx*4];
#pragma unroll
            for (int i = 0; i < 4; i++)
#pragma unroll
                for (int j = 0; j < 4; j++) acc[i][j] += a[i] * bb[j];
        }
        __syncthreads();
    }
#pragma unroll
    for (int i = 0; i < 4; i++) {
        int r = m0 + ty*4 + i;
        *(float4*)(Cp + (long)r*ldc + n0 + tx*4) =
            make_float4(acc[i][0], acc[i][1], acc[i][2], acc[i][3]);
    }
}

/* ------------------------- bf16-split HMMA GEMM (R8-proven) ------------------- */
#define SLDA 40   /* smem row stride in halfs (32 + 8 pad) */

__device__ __forceinline__ void mma_bf16(float* d, const uint32_t* a,
                                         const uint32_t* b) {
    asm volatile(
        "mma.sync.aligned.m16n8k16.row.col.f32.bf16.bf16.f32 "
        "{%0,%1,%2,%3}, {%4,%5,%6,%7}, {%8,%9}, {%0,%1,%2,%3};"
        : "+f"(d[0]), "+f"(d[1]), "+f"(d[2]), "+f"(d[3])
        : "r"(a[0]), "r"(a[1]), "r"(a[2]), "r"(a[3]), "r"(b[0]), "r"(b[1]));
}

__global__ void __launch_bounds__(256, 1)
k_hmma(const float* __restrict__ A, int lda,
       const float* __restrict__ Bt, int ldb,
       float* __restrict__ C, int ldc, int M, int K) {
    __shared__ __nv_bfloat16 sAh[128*SLDA], sAl[128*SLDA];
    __shared__ __nv_bfloat16 sBh[128*SLDA], sBl[128*SLDA];
    int tid = threadIdx.x, wid = tid >> 5, lane = tid & 31;
    int wm = wid & 3, wn = wid >> 2;          /* 4 x 2 warp grid */
    int g = lane >> 2, tg = lane & 3;
    int bm = blockIdx.y * 128, bn = blockIdx.x * 128;

    float acc[2][8][4];
#pragma unroll
    for (int i = 0; i < 2; i++)
#pragma unroll
        for (int j = 0; j < 8; j++)
#pragma unroll
            for (int r = 0; r < 4; r++) acc[i][j][r] = 0.f;

    for (int kc = 0; kc < K; kc += 32) {
#pragma unroll
        for (int it = 0; it < 4; it++) {
            int idx = tid + it*256;            /* 1024 float4 slots */
            int r = idx >> 3, c4 = (idx & 7) << 2;
            float4 va = make_float4(0.f, 0.f, 0.f, 0.f);
            if (bm + r < M) va = *(const float4*)(A + (long)(bm+r)*lda + kc + c4);
            __nv_bfloat162 h0 = __float22bfloat162_rn(make_float2(va.x, va.y));
            __nv_bfloat162 h1 = __float22bfloat162_rn(make_float2(va.z, va.w));
            float2 f0 = __bfloat1622float2(h0), f1 = __bfloat1622float2(h1);
            __nv_bfloat162 l0 = __float22bfloat162_rn(make_float2(va.x-f0.x, va.y-f0.y));
            __nv_bfloat162 l1 = __float22bfloat162_rn(make_float2(va.z-f1.x, va.w-f1.y));
            *(uint2*)&sAh[r*SLDA + c4] = make_uint2(*(uint32_t*)&h0, *(uint32_t*)&h1);
            *(uint2*)&sAl[r*SLDA + c4] = make_uint2(*(uint32_t*)&l0, *(uint32_t*)&l1);

            float4 vb = *(const float4*)(Bt + (long)(bn+r)*ldb + kc + c4);
            h0 = __float22bfloat162_rn(make_float2(vb.x, vb.y));
            h1 = __float22bfloat162_rn(make_float2(vb.z, vb.w));
            f0 = __bfloat1622float2(h0); f1 = __bfloat1622float2(h1);
            l0 = __float22bfloat162_rn(make_float2(vb.x-f0.x, vb.y-f0.y));
            l1 = __float22bfloat162_rn(make_float2(vb.z-f1.x, vb.w-f1.y));
            *(uint2*)&sBh[r*SLDA + c4] = make_uint2(*(uint32_t*)&h0, *(uint32_t*)&h1);
            *(uint2*)&sBl[r*SLDA + c4] = make_uint2(*(uint32_t*)&l0, *(uint32_t*)&l1);
        }
        __syncthreads();

#pragma unroll
        for (int ks = 0; ks < 32; ks += 16) {
            uint32_t ah[2][4], al[2][4];
#pragma unroll
            for (int mt = 0; mt < 2; mt++) {
                int r0 = (wm*32 + mt*16 + g) * SLDA + ks + tg*2;
                int r8 = r0 + 8*SLDA;
                ah[mt][0] = *(const uint32_t*)&sAh[r0];
                ah[mt][1] = *(const uint32_t*)&sAh[r8];
                ah[mt][2] = *(const uint32_t*)&sAh[r0 + 8];
                ah[mt][3] = *(const uint32_t*)&sAh[r8 + 8];
                al[mt][0] = *(const uint32_t*)&sAl[r0];
                al[mt][1] = *(const uint32_t*)&sAl[r8];
                al[mt][2] = *(const uint32_t*)&sAl[r0 + 8];
                al[mt][3] = *(const uint32_t*)&sAl[r8 + 8];
            }
#pragma unroll
            for (int nt = 0; nt < 8; nt++) {
                int n0 = (wn*64 + nt*8 + g) * SLDA + ks + tg*2;
                uint32_t bh[2], bl[2];
                bh[0] = *(const uint32_t*)&sBh[n0];
                bh[1] = *(const uint32_t*)&sBh[n0 + 8];
                bl[0] = *(const uint32_t*)&sBl[n0];
                bl[1] = *(const uint32_t*)&sBl[n0 + 8];
                mma_bf16(acc[0][nt], ah[0], bh);
                mma_bf16(acc[1][nt], ah[1], bh);
                mma_bf16(acc[0][nt], ah[0], bl);
                mma_bf16(acc[1][nt], ah[1], bl);
                mma_bf16(acc[0][nt], al[0], bh);
                mma_bf16(acc[1][nt], al[1], bh);
            }
        }
        __syncthreads();
    }

#pragma unroll
    for (int mt = 0; mt < 2; mt++) {
        int r0 = bm + wm*32 + mt*16 + g;
#pragma unroll
        for (int nt = 0; nt < 8; nt++) {
            int c0 = bn + wn*64 + nt*8 + tg*2;
            if (r0 < M)
                *(float2*)(C + (long)r0*ldc + c0) =
                    make_float2(acc[mt][nt][0], acc[mt][nt][1]);
            if (r0 + 8 < M)
                *(float2*)(C + (long)(r0+8)*ldc + c0) =
                    make_float2(acc[mt][nt][2], acc[mt][nt][3]);
        }
    }
}

/* ------------------------- GAT: softmax-mix in x-space (warp/row) ------------- */
__global__ __launch_bounds__(256) void k_gat_mix(int L) {
    int w = blockIdx.x*8 + (threadIdx.x >> 5);
    if (w >= NB) return;
    int lane = threadIdx.x & 31;
    int b = w / NN;
    int deg = g_adj_deg[w];
    const int* cols = g_adj_cols + (long)w * MAXDEG;
    int creg[4]; float e0r[4], e1r[4];
    float es0 = g_es0[w], es1 = g_es1[w];
    float m0 = -1e30f, m1 = -1e30f;
#pragma unroll
    for (int i = 0; i < 4; i++) {
        int j = i*32 + lane;
        creg[i] = 0; e0r[i] = -1e30f; e1r[i] = -1e30f;
        if (j < deg) {
            int c = cols[j]; creg[i] = c;
            float t0 = es0 + g_ed0[b*NN + c]; e0r[i] = (t0 > 0.f) ? t0 : 0.2f*t0;
            float t1 = es1 + g_ed1[b*NN + c]; e1r[i] = (t1 > 0.f) ? t1 : 0.2f*t1;
            m0 = fmaxf(m0, e0r[i]); m1 = fmaxf(m1, e1r[i]);
        }
    }
    m0 = wrmax(m0); m1 = wrmax(m1);
    float s0 = 0.f, s1 = 0.f;
    float p0r[4], p1r[4];
#pragma unroll
    for (int i = 0; i < 4; i++) {
        int j = i*32 + lane;
        p0r[i] = (j < deg) ? expf(e0r[i] - m0) : 0.f;
        p1r[i] = (j < deg) ? expf(e1r[i] - m1) : 0.f;
        s0 += p0r[i]; s1 += p1r[i];
    }
    s0 = wrsum(s0); s1 = wrsum(s1);
    float inv0 = 0.5f / s0, inv1 = 0.5f / s1;   /* fold head-mean */
    float4 a0 = make_float4(0.f, 0.f, 0.f, 0.f);
    float4 a1 = make_float4(0.f, 0.f, 0.f, 0.f);
    for (int i = 0; i < 4 && i*32 < deg; i++) {
        for (int l = 0; l < 32; l++) {
            int j = i*32 + l;
            if (j >= deg) break;                    /* uniform across warp */
            int   c  = __shfl_sync(0xffffffffu, creg[i], l);
            float w0 = __shfl_sync(0xffffffffu, p0r[i], l) * inv0;
            float w1 = __shfl_sync(0xffffffffu, p1r[i], l) * inv1;
            float4 x4 = *(const float4*)(g_seq + (long)(b*NN + c)*384 + L*128 + lane*4);
            a0.x += w0*x4.x; a0.y += w0*x4.y; a0.z += w0*x4.z; a0.w += w0*x4.w;
            a1.x += w1*x4.x; a1.y += w1*x4.y; a1.z += w1*x4.z; a1.w += w1*x4.w;
        }
    }
    *(float4*)(g_mix + (long)w*256       + lane*4) = a0;
    *(float4*)(g_mix + (long)w*256 + 128 + lane*4) = a1;
}

/* ------------------ GAT: elu + normalize -> seq slot (+ esed layer1) ---------- */
__global__ __launch_bounds__(256) void k_gat_post(int lslot, int doEsed) {
    int w = blockIdx.x*8 + (threadIdx.x >> 5);
    if (w >= NB) return;
    int lane = threadIdx.x & 31;
    float4 mv = *(const float4*)(g_mv + (long)w*DD + lane*4);
    float4 ev;
    ev.x = (mv.x > 0.f) ? mv.x : expm1f(mv.x);
    ev.y = (mv.y > 0.f) ? mv.y : expm1f(mv.y);
    ev.z = (mv.z > 0.f) ? mv.z : expm1f(mv.z);
    ev.w = (mv.w > 0.f) ? mv.w : expm1f(mv.w);
    float ss = wrsum(dot4(ev, ev));
    float nrm = 1.f / fmaxf(sqrtf(ss), 1e-12f);
    float4 r = make_float4(ev.x*nrm, ev.y*nrm, ev.z*nrm, ev.w*nrm);
    *(float4*)(g_seq + ((long)w*3 + lslot)*DD + lane*4) = r;
    if (doEsed) {
        const float* base = g_wsd + 512;       /* layer-1 vectors */
        float4 ws0 = *(const float4*)(base       + lane*4);
        float4 ws1 = *(const float4*)(base + 128 + lane*4);
        float4 wd0 = *(const float4*)(base + 256 + lane*4);
        float4 wd1 = *(const float4*)(base + 384 + lane*4);
        float v0 = wrsum(dot4(r, ws0));
        float v1 = wrsum(dot4(r, wd0));
        float v2 = wrsum(dot4(r, ws1));
        float v3 = wrsum(dot4(r, wd1));
        if (lane == 0) { g_es0[w] = v0; g_ed0[w] = v1; g_es1[w] = v2; g_ed1[w] = v3; }
    }
}

/* ------------------------- MHA: scores via y.x, mix x (warp/node) ------------- */
__global__ __launch_bounds__(256) void k_mha() {
    int w = blockIdx.x*8 + (threadIdx.x >> 5);
    if (w >= NB) return;
    int lane = threadIdx.x & 31;
    float4 x4[3], y4[3][2];
#pragma unroll
    for (int l = 0; l < 3; l++) {
        x4[l] = *(const float4*)(g_seq + (long)w*384 + l*128 + lane*4);
#pragma unroll
        for (int h = 0; h < 2; h++)
            y4[l][h] = *(const float4*)(g_y2 + (long)w*768 + l*256 + h*128 + lane*4);
    }
    float sc[2][3][3];
#pragma unroll
    for (int h = 0; h < 2; h++)
#pragma unroll
        for (int l = 0; l < 3; l++)
#pragma unroll
            for (int m = 0; m < 3; m++)
                sc[h][l][m] = wrsum(dot4(y4[l][h], x4[m])) * 0.08838834764831845f;
#pragma unroll
    for (int h = 0; h < 2; h++)
#pragma unroll
        for (int l = 0; l < 3; l++) {
            float a0 = sc[h][l][0], a1 = sc[h][l][1], a2 = sc[h][l][2];
            float m = fmaxf(a0, fmaxf(a1, a2));
            float e0 = expf(a0 - m), e1 = expf(a1 - m), e2 = expf(a2 - m);
            float inv = 1.f / (e0 + e1 + e2);
            e0 *= inv; e1 *= inv; e2 *= inv;
            float4 z;
            z.x = e0*x4[0].x + e1*x4[1].x + e2*x4[2].x;
            z.y = e0*x4[0].y + e1*x4[1].y + e2*x4[2].y;
            z.z = e0*x4[0].z + e1*x4[1].z + e2*x4[2].z;
            z.w = e0*x4[0].w + e1*x4[1].w + e2*x4[2].w;
            *(float4*)(g_z + (long)w*768 + l*256 + h*128 + lane*4) = z;
        }
}

/* ------------------------- residual + LN + mean (warp/row) -------------------- */
__global__ __launch_bounds__(256) void k_ln(const float* __restrict__ g,
                                            const float* __restrict__ bb,
                                            float* __restrict__ out) {
    int w = blockIdx.x*8 + (threadIdx.x >> 5);
    if (w >= NB) return;
    int lane = threadIdx.x & 31;
    int b = w / NN, row = w - b*NN;
    float4 g4 = *(const float4*)(g + lane*4);
    float4 b4 = *(const float4*)(bb + lane*4);
    float4 acc = make_float4(0.f, 0.f, 0.f, 0.f);
#pragma unroll
    for (int l = 0; l < 3; l++) {
        float4 v0 = *(const float4*)(g_of + ((long)w*3 + l)*DD + lane*4);
        float4 v1 = *(const float4*)(g_seq + ((long)w*3 + l)*DD + lane*4);
        float4 v = make_float4(v0.x+v1.x, v0.y+v1.y, v0.z+v1.z, v0.w+v1.w);
        float s  = wrsum(v.x + v.y + v.z + v.w);
        float s2 = wrsum(dot4(v, v));
        float mu  = s * (1.f/128.f);
        float var = s2 * (1.f/128.f) - mu*mu;
        float is = rsqrtf(var + 1e-6f);
        acc.x += g4.x*(v.x - mu)*is + b4.x;
        acc.y += g4.y*(v.y - mu)*is + b4.y;
        acc.z += g4.z*(v.z - mu)*is + b4.z;
        acc.w += g4.w*(v.w - mu)*is + b4.w;
    }
    float4 r = make_float4(acc.x*(1.f/3.f), acc.y*(1.f/3.f),
                           acc.z*(1.f/3.f), acc.w*(1.f/3.f));
    *(float4*)(out + (long)b*NN*256 + (long)row*256 + lane*4) = r;
}

/* ------------------------- HGC pieces (warp/row) ------------------------------ */
__global__ __launch_bounds__(256) void k_hgc_bias(const float* __restrict__ T,
                                                  const float* __restrict__ bvec,
                                                  float* __restrict__ Y) {
    int w = blockIdx.x*8 + (threadIdx.x >> 5);
    if (w >= NB) return;
    int lane = threadIdx.x & 31;
    float4 t4 = *(const float4*)(T + (long)w*DD + lane*4);
    float4 b4 = *(const float4*)(bvec + lane*4);
    float s0 = wrsum(dot4(t4, t4));
    float s1 = wrsum(dot4(b4, b4));
    float s2 = wrsum(dot4(t4, b4));
    float nt = fmaxf(sqrtf(s0), 1e-15f);
    float et = tanhf(nt);
    float pt = (et > MAXN_) ? MAXN_/et : 1.f;
    float cm = (et/nt) * pt;
    float x2 = (et*pt) * (et*pt);
    float nb = fmaxf(sqrtf(s1), 1e-15f);
    float eb = tanhf(nb);
    float pb = (eb > MAXN_) ? MAXN_/eb : 1.f;
    float cb = (eb/nb) * pb;
    float y2 = (eb*pb) * (eb*pb);
    float xy = cm * cb * s2;
    float den = fmaxf(1.f + 2.f*xy + x2*y2, 1e-15f);
    float fA = (1.f + 2.f*xy + y2) * cm / den;
    float fB = (1.f - x2) * cb / den;
    float4 r = make_float4(fA*t4.x + fB*b4.x, fA*t4.y + fB*b4.y,
                           fA*t4.z + fB*b4.z, fA*t4.w + fB*b4.w);
    float s3 = wrsum(dot4(r, r));
    float nr = fmaxf(sqrtf(s3), 1e-15f);
    float pr = (nr > MAXN_) ? MAXN_/nr : 1.f;
    float np = fmaxf(nr*pr, 1e-15f);
    float c2 = atanhf(fminf(np, 1.f - 1e-7f)) / np * pr;
    *(float4*)(Y + (long)w*DD + lane*4) =
        make_float4(c2*r.x, c2*r.y, c2*r.z, c2*r.w);
}

/* final==0: write W buffer.  final==1: write out[(2+b)] with ent residual. ----- */
__global__ __launch_bounds__(256) void k_hgc_agg(const float* __restrict__ Y,
                                                 float* __restrict__ W,
                                                 const float* __restrict__ e0,
                                                 const float* __restrict__ e1,
                                                 float* __restrict__ out,
                                                 int final_) {
    int w = blockIdx.x*8 + (threadIdx.x >> 5);
    if (w >= NB) return;
    int lane = threadIdx.x & 31;
    int b = w / NN, row = w - b*NN;
    const int* cols = g_adj_cols + (long)w * MAXDEG;
    int deg = g_adj_deg[w];
    float4 acc = make_float4(0.f, 0.f, 0.f, 0.f);
    for (int j = 0; j < deg; j++) {
        int c = __ldg(&cols[j]);
        float4 v = *(const float4*)(Y + (long)(b*NN + c)*DD + lane*4);
        acc.x += v.x; acc.y += v.y; acc.z += v.z; acc.w += v.w;
    }
    float inv = 1.f / (float)deg;
    float4 z = make_float4(acc.x*inv, acc.y*inv, acc.z*inv, acc.w*inv);
    float4 rz = make_float4(fmaxf(z.x, 0.f), fmaxf(z.y, 0.f),
                            fmaxf(z.z, 0.f), fmaxf(z.w, 0.f));
    float s0 = wrsum(dot4(z, z));
    float s1 = wrsum(dot4(rz, rz));
    float nz = fmaxf(sqrtf(s0), 1e-15f);
    float e1v = tanhf(nz);
    float p1 = (e1v > MAXN_) ? MAXN_/e1v : 1.f;
    float cH = (e1v/nz) * p1;
    float nH = fmaxf(e1v*p1, 1e-15f);
    float cT = atanhf(fminf(nH, 1.f - 1e-7f)) / nH * cH;
    float nt2 = fmaxf(cT * sqrtf(s1), 1e-15f);
    float e2 = tanhf(nt2);
    float p2 = (e2 > MAXN_) ? MAXN_/e2 : 1.f;
    float hcoef = (e2/nt2) * p2 * cT;
    float nH2 = fmaxf(e2*p2, 1e-15f);
    float c2 = atanhf(fminf(nH2, 1.f - 1e-7f)) / nH2;
    float cc = c2 * hcoef;
    if (final_) {
        float4 e = *(const float4*)((b ? e1 : e0) + (long)row*DD + lane*4);
        *(float4*)(out + (long)(2+b)*NN*256 + (long)row*256 + lane*4) =
            make_float4(e.x + cc*rz.x, e.y + cc*rz.y, e.z + cc*rz.z, e.w + cc*rz.w);
    } else {
        *(float4*)(W + (long)w*DD + lane*4) =
            make_float4(cc*rz.x, cc*rz.y, cc*rz.z, cc*rz.w);
    }
}

/* ------------------------- host driver ----------------------------------------- */
extern "C" void kernel_launch(void* const* d_in, const int* in_sizes, int n_in,
                              void* d_out, int out_size) {
    const float* ent_sr    = (const float*)d_in[0];
    const float* ent_tg    = (const float*)d_in[1];
    const float* rel_sr    = (const float*)d_in[2];
    const float* rel_tg    = (const float*)d_in[3];
    const float* adj_sr    = (const float*)d_in[4];
    const float* adj_tg    = (const float*)d_in[5];
    const float* rel_adj_sr= (const float*)d_in[6];
    const float* rel_adj_tg= (const float*)d_in[7];
    const float* gat_W     = (const float*)d_in[8];
    const float* gat_a_src = (const float*)d_in[9];
    const float* gat_a_dst = (const float*)d_in[10];
    const float* Wq        = (const float*)d_in[11];
    const float* Wk        = (const float*)d_in[12];
    const float* Wv        = (const float*)d_in[13];
    const float* Wfc       = (const float*)d_in[14];
    const float* ln_g      = (const float*)d_in[15];
    const float* ln_b      = (const float*)d_in[16];
    const float* hgc_W     = (const float*)d_in[17];
    const float* hgc_b     = (const float*)d_in[18];
    float* out = (float*)d_out;

    float *seq, *mix, *mv, *y2, *z, *of, *u, *t, *y, *w, *Gt, *Pt, *Wgt;
    cudaGetSymbolAddress((void**)&seq, g_seq);
    cudaGetSymbolAddress((void**)&mix, g_mix);
    cudaGetSymbolAddress((void**)&mv,  g_mv);
    cudaGetSymbolAddress((void**)&y2,  g_y2);
    cudaGetSymbolAddress((void**)&z,   g_z);
    cudaGetSymbolAddress((void**)&of,  g_of);
    cudaGetSymbolAddress((void**)&u,   g_u);
    cudaGetSymbolAddress((void**)&t,   g_t);
    cudaGetSymbolAddress((void**)&y,   g_y);
    cudaGetSymbolAddress((void**)&w,   g_w);
    cudaGetSymbolAddress((void**)&Gt,  g_Gt);
    cudaGetSymbolAddress((void**)&Pt,  g_Pt);
    cudaGetSymbolAddress((void**)&Wgt, g_Wgt);

    dim3 gGAT(1, 94);      /* [12000,256]@Wgt^T -> N=128 */
    dim3 gY  (2, 282);     /* [36000,128]@Gt^T  -> N=256 */
    dim3 gOF (1, 282);     /* [36000,256]@Pt^T  -> N=128 */
    dim3 gHGC(1, 94);

    /* sparsify + precompute */
    k_build_adj<<<dim3(NN, 2), 256>>>(adj_sr, adj_tg);
    k_build_rel<<<dim3(NN, 2), 256>>>(rel_adj_sr, rel_adj_tg);
    k_relagg<<<NWB, 256>>>(rel_sr, rel_tg, out);
    k_pre4<<<16, 256>>>(Wq, Wk, Wv, Wfc);
    k_precomp_gat<<<8, 128>>>(gat_W, gat_a_src, gat_a_dst);
    k_precomp_Wgt<<<256, 256>>>(gat_W);
    k_seq0e<<<NWB, 256>>>(ent_sr, ent_tg);     /* copy + esed layer0 + u0 */

    /* GAT x2 */
    for (int L = 0; L < 2; L++) {
        k_gat_mix<<<NWB, 256>>>(L);
        k_hmma<<<gGAT, 256>>>(mix, 256, Wgt + (long)L*128*256, 256,
                              mv, 128, 12000, 256);
        k_gat_post<<<NWB, 256>>>(L + 1, L == 0 ? 1 : 0);
    }

    /* MHA */
    k_hmma<<<gY, 256>>>(seq, 128, Gt, 128, y2, 256, 36000, 128);
    k_mha<<<NWB, 256>>>();
    k_hmma<<<gOF, 256>>>(z, 256, Pt, 256, of, 128, 36000, 256);
    k_ln<<<NWB, 256>>>(ln_g, ln_b, out);

    /* HGC encoder */
    k_hmma<<<gHGC, 256>>>(u, 128, hgc_W, 128, t, 128, 12000, 128);
    k_hgc_bias<<<NWB, 256>>>(t, hgc_b, y);
    k_hgc_agg<<<NWB, 256>>>(y, w, ent_sr, ent_tg, out, 0);
    k_hmma<<<gHGC, 256>>>(w, 128, hgc_W + DD*DD, 128, t, 128, 12000, 128);
    k_hgc_bias<<<NWB, 256>>>(t, hgc_b + DD, y);
    k_hgc_agg<<<NWB, 256>>>(y, w, ent_sr, ent_tg, out, 1);
}

// round 15
// speedup vs baseline: 1.6129x; 1.1021x over previous
#include <cuda_runtime.h>
#include <cuda_bf16.h>
#include <math.h>
#include <stdint.h>

#define NN      6000
#define DD      128
#define RR      1000
#define MAXDEG  128
#define MAXRDEG 64
#define NB      12000     /* 2*NN: both branches stacked */
#define NWB     1500      /* NB/8 warp-per-row grid */
#define MAXN_   0.996f    /* 1 - 4e-3 */

/* ------------------------- static scratch (no allocs) ------------------------- */
__device__ __align__(16) float g_seq[(long)NB*3*DD];
__device__ __align__(16) float g_mix[(long)NB*2*DD];
__device__ __align__(16) float g_mv [(long)NB*DD];
__device__ float g_es0[NB], g_ed0[NB], g_es1[NB], g_ed1[NB];
__device__ __align__(16) float g_y2[(long)NB*3*2*DD];
__device__ __align__(16) float g_z [(long)NB*3*2*DD];
__device__ __align__(16) float g_of[(long)NB*3*DD];
__device__ __align__(16) float g_u [(long)NB*DD];
__device__ __align__(16) float g_t [(long)NB*DD];
__device__ __align__(16) float g_y [(long)NB*DD];
__device__ __align__(16) float g_w [(long)NB*DD];
__device__ __align__(16) float g_Gt [2*DD*DD];
__device__ __align__(16) float g_Pt [DD*2*DD];
__device__ __align__(16) float g_Wgt[2*DD*2*DD];
__device__ __align__(16) float g_wsd[2*2*2*DD];
__device__ int g_adj_cols[(long)NB*MAXDEG];
__device__ int g_adj_deg[NB];
__device__ int g_rel_cols[(long)NB*MAXRDEG];
__device__ int g_rel_deg[NB];

/* ------------------------- warp helpers --------------------------------------- */
__device__ __forceinline__ float wrsum(float x) {
#pragma unroll
    for (int o = 16; o; o >>= 1) x += __shfl_xor_sync(0xffffffffu, x, o);
    return x;
}
__device__ __forceinline__ float wrmax(float x) {
#pragma unroll
    for (int o = 16; o; o >>= 1) x = fmaxf(x, __shfl_xor_sync(0xffffffffu, x, o));
    return x;
}
__device__ __forceinline__ float dot4(float4 a, float4 b) {
    return a.x*b.x + a.y*b.y + a.z*b.z + a.w*b.w;
}

/* ------------------------- device bodies (warp/row) --------------------------- */
__device__ __forceinline__ void dev_relagg(int w, int lane,
                                           const float* __restrict__ r0,
                                           const float* __restrict__ r1,
                                           float* __restrict__ out) {
    int b = w / NN, row = w - b*NN;
    const float* remb = b ? r1 : r0;
    const int* cols = g_rel_cols + (long)w * MAXRDEG;
    int deg = g_rel_deg[w];
    float4 acc = make_float4(0.f, 0.f, 0.f, 0.f);
    for (int j = 0; j < deg; j++) {
        int c = __ldg(&cols[j]);
        float4 v = *(const float4*)(remb + (long)c*DD + lane*4);
        acc.x += v.x; acc.y += v.y; acc.z += v.z; acc.w += v.w;
    }
    float inv = 1.f / (float)deg;
    float4 r = make_float4(acc.x*inv, acc.y*inv, acc.z*inv, acc.w*inv);
    *(float4*)(out + (long)b*NN*256 + (long)row*256 + 128 + lane*4) = r;
    *(float4*)(out + (long)(2+b)*NN*256 + (long)row*256 + 128 + lane*4) = r;
}

__device__ __forceinline__ void dev_seq0e(int w, int lane,
                                          const float* __restrict__ e0,
                                          const float* __restrict__ e1) {
    int b = w / NN, row = w - b*NN;
    float4 x4 = *(const float4*)((b ? e1 : e0) + (long)row*DD + lane*4);
    *(float4*)(g_seq + (long)w*384 + lane*4) = x4;
    float4 ws0 = *(const float4*)(g_wsd       + lane*4);
    float4 ws1 = *(const float4*)(g_wsd + 128 + lane*4);
    float4 wd0 = *(const float4*)(g_wsd + 256 + lane*4);
    float4 wd1 = *(const float4*)(g_wsd + 384 + lane*4);
    float v0 = wrsum(dot4(x4, ws0));
    float v1 = wrsum(dot4(x4, wd0));
    float v2 = wrsum(dot4(x4, ws1));
    float v3 = wrsum(dot4(x4, wd1));
    if (lane == 0) { g_es0[w] = v0; g_ed0[w] = v1; g_es1[w] = v2; g_ed1[w] = v3; }
    float s = wrsum(dot4(x4, x4));
    float n0 = fmaxf(sqrtf(s), 1e-15f);
    float ne = tanhf(n0);
    float pe = (ne > MAXN_) ? MAXN_/ne : 1.f;
    float np = fmaxf(ne*pe, 1e-15f);
    float c  = atanhf(fminf(np, 1.f - 1e-7f)) / np * (ne / n0) * pe;
    *(float4*)(g_u + (long)w*DD + lane*4) =
        make_float4(c*x4.x, c*x4.y, c*x4.z, c*x4.w);
}

__device__ __forceinline__ void dev_gat_mix(int w, int lane, int L) {
    int b = w / NN;
    int deg = g_adj_deg[w];
    const int* cols = g_adj_cols + (long)w * MAXDEG;
    int creg[4]; float e0r[4], e1r[4];
    float es0 = g_es0[w], es1 = g_es1[w];
    float m0 = -1e30f, m1 = -1e30f;
#pragma unroll
    for (int i = 0; i < 4; i++) {
        int j = i*32 + lane;
        creg[i] = 0; e0r[i] = -1e30f; e1r[i] = -1e30f;
        if (j < deg) {
            int c = cols[j]; creg[i] = c;
            float t0 = es0 + g_ed0[b*NN + c]; e0r[i] = (t0 > 0.f) ? t0 : 0.2f*t0;
            float t1 = es1 + g_ed1[b*NN + c]; e1r[i] = (t1 > 0.f) ? t1 : 0.2f*t1;
            m0 = fmaxf(m0, e0r[i]); m1 = fmaxf(m1, e1r[i]);
        }
    }
    m0 = wrmax(m0); m1 = wrmax(m1);
    float s0 = 0.f, s1 = 0.f;
    float p0r[4], p1r[4];
#pragma unroll
    for (int i = 0; i < 4; i++) {
        int j = i*32 + lane;
        p0r[i] = (j < deg) ? expf(e0r[i] - m0) : 0.f;
        p1r[i] = (j < deg) ? expf(e1r[i] - m1) : 0.f;
        s0 += p0r[i]; s1 += p1r[i];
    }
    s0 = wrsum(s0); s1 = wrsum(s1);
    float inv0 = 0.5f / s0, inv1 = 0.5f / s1;
    float4 a0 = make_float4(0.f, 0.f, 0.f, 0.f);
    float4 a1 = make_float4(0.f, 0.f, 0.f, 0.f);
    for (int i = 0; i < 4 && i*32 < deg; i++) {
        for (int l = 0; l < 32; l++) {
            int j = i*32 + l;
            if (j >= deg) break;
            int   c  = __shfl_sync(0xffffffffu, creg[i], l);
            float w0 = __shfl_sync(0xffffffffu, p0r[i], l) * inv0;
            float w1 = __shfl_sync(0xffffffffu, p1r[i], l) * inv1;
            float4 x4 = *(const float4*)(g_seq + (long)(b*NN + c)*384 + L*128 + lane*4);
            a0.x += w0*x4.x; a0.y += w0*x4.y; a0.z += w0*x4.z; a0.w += w0*x4.w;
            a1.x += w1*x4.x; a1.y += w1*x4.y; a1.z += w1*x4.z; a1.w += w1*x4.w;
        }
    }
    *(float4*)(g_mix + (long)w*256       + lane*4) = a0;
    *(float4*)(g_mix + (long)w*256 + 128 + lane*4) = a1;
}

__device__ __forceinline__ void dev_gat_post(int w, int lane, int lslot, int doEsed) {
    float4 mv = *(const float4*)(g_mv + (long)w*DD + lane*4);
    float4 ev;
    ev.x = (mv.x > 0.f) ? mv.x : expm1f(mv.x);
    ev.y = (mv.y > 0.f) ? mv.y : expm1f(mv.y);
    ev.z = (mv.z > 0.f) ? mv.z : expm1f(mv.z);
    ev.w = (mv.w > 0.f) ? mv.w : expm1f(mv.w);
    float ss = wrsum(dot4(ev, ev));
    float nrm = 1.f / fmaxf(sqrtf(ss), 1e-12f);
    float4 r = make_float4(ev.x*nrm, ev.y*nrm, ev.z*nrm, ev.w*nrm);
    *(float4*)(g_seq + ((long)w*3 + lslot)*DD + lane*4) = r;
    if (doEsed) {
        const float* base = g_wsd + 512;
        float4 ws0 = *(const float4*)(base       + lane*4);
        float4 ws1 = *(const float4*)(base + 128 + lane*4);
        float4 wd0 = *(const float4*)(base + 256 + lane*4);
        float4 wd1 = *(const float4*)(base + 384 + lane*4);
        float v0 = wrsum(dot4(r, ws0));
        float v1 = wrsum(dot4(r, wd0));
        float v2 = wrsum(dot4(r, ws1));
        float v3 = wrsum(dot4(r, wd1));
        if (lane == 0) { g_es0[w] = v0; g_ed0[w] = v1; g_es1[w] = v2; g_ed1[w] = v3; }
    }
}

__device__ __forceinline__ void dev_hgc_bias(int w, int lane,
                                             const float* __restrict__ T,
                                             const float* __restrict__ bvec,
                                             float* __restrict__ Y) {
    float4 t4 = *(const float4*)(T + (long)w*DD + lane*4);
    float4 b4 = *(const float4*)(bvec + lane*4);
    float s0 = wrsum(dot4(t4, t4));
    float s1 = wrsum(dot4(b4, b4));
    float s2 = wrsum(dot4(t4, b4));
    float nt = fmaxf(sqrtf(s0), 1e-15f);
    float et = tanhf(nt);
    float pt = (et > MAXN_) ? MAXN_/et : 1.f;
    float cm = (et/nt) * pt;
    float x2 = (et*pt) * (et*pt);
    float nb = fmaxf(sqrtf(s1), 1e-15f);
    float eb = tanhf(nb);
    float pb = (eb > MAXN_) ? MAXN_/eb : 1.f;
    float cb = (eb/nb) * pb;
    float y2 = (eb*pb) * (eb*pb);
    float xy = cm * cb * s2;
    float den = fmaxf(1.f + 2.f*xy + x2*y2, 1e-15f);
    float fA = (1.f + 2.f*xy + y2) * cm / den;
    float fB = (1.f - x2) * cb / den;
    float4 r = make_float4(fA*t4.x + fB*b4.x, fA*t4.y + fB*b4.y,
                           fA*t4.z + fB*b4.z, fA*t4.w + fB*b4.w);
    float s3 = wrsum(dot4(r, r));
    float nr = fmaxf(sqrtf(s3), 1e-15f);
    float pr = (nr > MAXN_) ? MAXN_/nr : 1.f;
    float np = fmaxf(nr*pr, 1e-15f);
    float c2 = atanhf(fminf(np, 1.f - 1e-7f)) / np * pr;
    *(float4*)(Y + (long)w*DD + lane*4) =
        make_float4(c2*r.x, c2*r.y, c2*r.z, c2*r.w);
}

__device__ __forceinline__ void dev_hgc_agg(int w, int lane,
                                            const float* __restrict__ Y,
                                            float* __restrict__ W,
                                            const float* __restrict__ e0,
                                            const float* __restrict__ e1,
                                            float* __restrict__ out, int final_) {
    int b = w / NN, row = w - b*NN;
    const int* cols = g_adj_cols + (long)w * MAXDEG;
    int deg = g_adj_deg[w];
    float4 acc = make_float4(0.f, 0.f, 0.f, 0.f);
    for (int j = 0; j < deg; j++) {
        int c = __ldg(&cols[j]);
        float4 v = *(const float4*)(Y + (long)(b*NN + c)*DD + lane*4);
        acc.x += v.x; acc.y += v.y; acc.z += v.z; acc.w += v.w;
    }
    float inv = 1.f / (float)deg;
    float4 z = make_float4(acc.x*inv, acc.y*inv, acc.z*inv, acc.w*inv);
    float4 rz = make_float4(fmaxf(z.x, 0.f), fmaxf(z.y, 0.f),
                            fmaxf(z.z, 0.f), fmaxf(z.w, 0.f));
    float s0 = wrsum(dot4(z, z));
    float s1 = wrsum(dot4(rz, rz));
    float nz = fmaxf(sqrtf(s0), 1e-15f);
    float e1v = tanhf(nz);
    float p1 = (e1v > MAXN_) ? MAXN_/e1v : 1.f;
    float cH = (e1v/nz) * p1;
    float nH = fmaxf(e1v*p1, 1e-15f);
    float cT = atanhf(fminf(nH, 1.f - 1e-7f)) / nH * cH;
    float nt2 = fmaxf(cT * sqrtf(s1), 1e-15f);
    float e2 = tanhf(nt2);
    float p2 = (e2 > MAXN_) ? MAXN_/e2 : 1.f;
    float hcoef = (e2/nt2) * p2 * cT;
    float nH2 = fmaxf(e2*p2, 1e-15f);
    float c2 = atanhf(fminf(nH2, 1.f - 1e-7f)) / nH2;
    float cc = c2 * hcoef;
    if (final_) {
        float4 e = *(const float4*)((b ? e1 : e0) + (long)row*DD + lane*4);
        *(float4*)(out + (long)(2+b)*NN*256 + (long)row*256 + lane*4) =
            make_float4(e.x + cc*rz.x, e.y + cc*rz.y, e.z + cc*rz.z, e.w + cc*rz.w);
    } else {
        *(float4*)(W + (long)w*DD + lane*4) =
            make_float4(cc*rz.x, cc*rz.y, cc*rz.z, cc*rz.w);
    }
}

__device__ __forceinline__ void dev_mha(int w, int lane) {
    float4 x4[3], y4[3][2];
#pragma unroll
    for (int l = 0; l < 3; l++) {
        x4[l] = *(const float4*)(g_seq + (long)w*384 + l*128 + lane*4);
#pragma unroll
        for (int h = 0; h < 2; h++)
            y4[l][h] = *(const float4*)(g_y2 + (long)w*768 + l*256 + h*128 + lane*4);
    }
    float sc[2][3][3];
#pragma unroll
    for (int h = 0; h < 2; h++)
#pragma unroll
        for (int l = 0; l < 3; l++)
#pragma unroll
            for (int m = 0; m < 3; m++)
                sc[h][l][m] = wrsum(dot4(y4[l][h], x4[m])) * 0.08838834764831845f;
#pragma unroll
    for (int h = 0; h < 2; h++)
#pragma unroll
        for (int l = 0; l < 3; l++) {
            float a0 = sc[h][l][0], a1 = sc[h][l][1], a2 = sc[h][l][2];
            float m = fmaxf(a0, fmaxf(a1, a2));
            float e0 = expf(a0 - m), e1 = expf(a1 - m), e2 = expf(a2 - m);
            float inv = 1.f / (e0 + e1 + e2);
            e0 *= inv; e1 *= inv; e2 *= inv;
            float4 z;
            z.x = e0*x4[0].x + e1*x4[1].x + e2*x4[2].x;
            z.y = e0*x4[0].y + e1*x4[1].y + e2*x4[2].y;
            z.z = e0*x4[0].z + e1*x4[1].z + e2*x4[2].z;
            z.w = e0*x4[0].w + e1*x4[1].w + e2*x4[2].w;
            *(float4*)(g_z + (long)w*768 + l*256 + h*128 + lane*4) = z;
        }
}

/* ------------------------- prep1: all independent prep work ------------------- */
__global__ __launch_bounds__(256) void k_prep1(
    const float* __restrict__ adj0, const float* __restrict__ adj1,
    const float* __restrict__ rel0, const float* __restrict__ rel1,
    const float* __restrict__ Wq, const float* __restrict__ Wk,
    const float* __restrict__ Wv, const float* __restrict__ Wfc,
    const float* __restrict__ gatW, const float* __restrict__ asrc,
    const float* __restrict__ adst) {
    __shared__ float shm[2*16*68];
    __shared__ int cnt;
    int bid = blockIdx.x;
    if (bid < 12000) {                               /* build_adj */
        int b = bid / NN, row = bid - b*NN;
        const float4* adj = (const float4*)((b ? adj1 : adj0) + (long)row * NN);
        if (threadIdx.x == 0) cnt = 0;
        __syncthreads();
        int* mc = g_adj_cols + (long)bid * MAXDEG;
        for (int c = threadIdx.x; c < NN/4; c += 256) {
            float4 v = adj[c];
            if (v.x > 0.f) { int p = atomicAdd(&cnt, 1); if (p < MAXDEG) mc[p] = c*4;   }
            if (v.y > 0.f) { int p = atomicAdd(&cnt, 1); if (p < MAXDEG) mc[p] = c*4+1; }
            if (v.z > 0.f) { int p = atomicAdd(&cnt, 1); if (p < MAXDEG) mc[p] = c*4+2; }
            if (v.w > 0.f) { int p = atomicAdd(&cnt, 1); if (p < MAXDEG) mc[p] = c*4+3; }
        }
        __syncthreads();
        if (threadIdx.x == 0) g_adj_deg[bid] = min(cnt, MAXDEG);
    } else if (bid < 24000) {                        /* build_rel */
        int n = bid - 12000;
        int b = n / NN, row = n - b*NN;
        const float4* adj = (const float4*)((b ? rel1 : rel0) + (long)row * RR);
        if (threadIdx.x == 0) cnt = 0;
        __syncthreads();
        int* mc = g_rel_cols + (long)n * MAXRDEG;
        for (int c = threadIdx.x; c < RR/4; c += 256) {
            float4 v = adj[c];
            if (v.x > 0.f) { int p = atomicAdd(&cnt, 1); if (p < MAXRDEG) mc[p] = c*4;   }
            if (v.y > 0.f) { int p = atomicAdd(&cnt, 1); if (p < MAXRDEG) mc[p] = c*4+1; }
            if (v.z > 0.f) { int p = atomicAdd(&cnt, 1); if (p < MAXRDEG) mc[p] = c*4+2; }
            if (v.w > 0.f) { int p = atomicAdd(&cnt, 1); if (p < MAXRDEG) mc[p] = c*4+3; }
        }
        __syncthreads();
        if (threadIdx.x == 0) g_rel_deg[n] = min(cnt, MAXRDEG);
    } else if (bid < 24016) {                        /* pre4: Gt/Pt quadrants */
        float* As = shm;
        float* Bs = shm + 16*68;
        int id = bid - 24000;
        int gid = id >> 2, quad = id & 3;
        int h = gid & 1, which = gid >> 1;
        int m0 = (quad >> 1) * 64, n0 = (quad & 1) * 64;
        const float *Ap, *Bp;
        float* Cp;
        int lda, amode, ldc;
        if (which == 0) {
            Ap = Wk + h*128;       lda = 256; amode = 0;
            Bp = Wq + h*128;
            Cp = g_Gt + h*128*128; ldc = 128;
        } else {
            Ap = Wfc + h*128*128;  lda = 128; amode = 1;
            Bp = Wv + h*128;
            Cp = g_Pt + h*128;     ldc = 256;
        }
        int tid = threadIdx.x;
        int tx = tid & 15, ty = tid >> 4;
        float acc[4][4];
#pragma unroll
        for (int i = 0; i < 4; i++)
#pragma unroll
            for (int j = 0; j < 4; j++) acc[i][j] = 0.f;
        for (int k0 = 0; k0 < 128; k0 += 16) {
            if (amode == 0) {
                int r = tid >> 2, c = (tid & 3) << 2;
                float4 av = *(const float4*)(Ap + (long)(m0 + r)*lda + k0 + c);
                As[c*68+r]=av.x; As[(c+1)*68+r]=av.y; As[(c+2)*68+r]=av.z; As[(c+3)*68+r]=av.w;
            } else {
                int r = tid >> 4, c = (tid & 15) << 2;
                *(float4*)&As[r*68+c] = *(const float4*)(Ap + (long)(k0+r)*lda + m0 + c);
            }
            {
                int n = tid >> 2, c = (tid & 3) << 2;
                float4 bv = *(const float4*)(Bp + (long)(n0 + n)*256 + k0 + c);
                Bs[c*68+n]=bv.x; Bs[(c+1)*68+n]=bv.y; Bs[(c+2)*68+n]=bv.z; Bs[(c+3)*68+n]=bv.w;
            }
            __syncthreads();
#pragma unroll
            for (int kk = 0; kk < 16; kk++) {
                float a[4], bb[4];
                *(float4*)&a[0]  = *(const float4*)&As[kk*68 + ty*4];
                *(float4*)&bb[0] = *(const float4*)&Bs[kk*68 + tx*4];
#pragma unroll
                for (int i = 0; i < 4; i++)
#pragma unroll
                    for (int j = 0; j < 4; j++) acc[i][j] += a[i] * bb[j];
            }
            __syncthreads();
        }
#pragma unroll
        for (int i = 0; i < 4; i++) {
            int r = m0 + ty*4 + i;
            *(float4*)(Cp + (long)r*ldc + n0 + tx*4) =
                make_float4(acc[i][0], acc[i][1], acc[i][2], acc[i][3]);
        }
    } else if (bid < 24024) {                        /* precomp_gat */
        int bi = bid - 24016, d = threadIdx.x;
        if (d < 128) {
            int L = bi >> 2, s = (bi >> 1) & 1, h = bi & 1;
            const float* a = (s ? adst : asrc) + (L*2 + h)*128;
            const float* wr = gatW + (long)((L*2 + h)*128 + d)*128;
            float acc = 0.f;
            for (int e = 0; e < 128; e++) acc += wr[e] * a[e];
            g_wsd[bi*128 + d] = acc;
        }
    } else {                                         /* precomp_Wgt */
        int idx = (bid - 24024)*256 + threadIdx.x;
        int e = idx & 127, d = (idx >> 7) & 127, h = (idx >> 14) & 1, L = idx >> 15;
        g_Wgt[((long)L*128 + e)*256 + h*128 + d] = gatW[idx];
    }
}

/* ------------------------- prep2: relagg || seq0e ----------------------------- */
__global__ __launch_bounds__(256) void k_prep2(const float* __restrict__ r0,
                                               const float* __restrict__ r1,
                                               float* __restrict__ out,
                                               const float* __restrict__ e0,
                                               const float* __restrict__ e1) {
    int bid = blockIdx.x;
    int lane = threadIdx.x & 31;
    if (bid < NWB) {
        int w = bid*8 + (threadIdx.x >> 5);
        dev_relagg(w, lane, r0, r1, out);
    } else {
        int w = (bid - NWB)*8 + (threadIdx.x >> 5);
        dev_seq0e(w, lane, e0, e1);
    }
}

/* ------------------------- thin warp/row kernels ------------------------------ */
__global__ __launch_bounds__(256) void k_gat_mix(int L) {
    int w = blockIdx.x*8 + (threadIdx.x >> 5);
    dev_gat_mix(w, threadIdx.x & 31, L);
}
/* gat_post || hgc_bias */
__global__ __launch_bounds__(256) void k_pb(int lslot, int doEsed,
                                            const float* __restrict__ bvec) {
    int bid = blockIdx.x;
    int lane = threadIdx.x & 31;
    if (bid < NWB) dev_gat_post(bid*8 + (threadIdx.x >> 5), lane, lslot, doEsed);
    else           dev_hgc_bias((bid - NWB)*8 + (threadIdx.x >> 5), lane, g_t, bvec, g_y);
}
/* gat_mix(L) || hgc_agg(y->w) */
__global__ __launch_bounds__(256) void k_ma(int L) {
    int bid = blockIdx.x;
    int lane = threadIdx.x & 31;
    if (bid < NWB) dev_gat_mix(bid*8 + (threadIdx.x >> 5), lane, L);
    else           dev_hgc_agg((bid - NWB)*8 + (threadIdx.x >> 5), lane,
                               g_y, g_w, 0, 0, 0, 0);
}
/* mha || hgc_agg final */
__global__ __launch_bounds__(256) void k_mhaF(const float* __restrict__ e0,
                                              const float* __restrict__ e1,
                                              float* __restrict__ out) {
    int bid = blockIdx.x;
    int lane = threadIdx.x & 31;
    if (bid < NWB) dev_mha(bid*8 + (threadIdx.x >> 5), lane);
    else           dev_hgc_agg((bid - NWB)*8 + (threadIdx.x >> 5), lane,
                               g_y, g_w, e0, e1, out, 1);
}

/* ------------------------- residual + LN + mean (warp/row) -------------------- */
__global__ __launch_bounds__(256) void k_ln(const float* __restrict__ g,
                                            const float* __restrict__ bb,
                                            float* __restrict__ out) {
    int w = blockIdx.x*8 + (threadIdx.x >> 5);
    int lane = threadIdx.x & 31;
    int b = w / NN, row = w - b*NN;
    float4 g4 = *(const float4*)(g + lane*4);
    float4 b4 = *(const float4*)(bb + lane*4);
    float4 acc = make_float4(0.f, 0.f, 0.f, 0.f);
#pragma unroll
    for (int l = 0; l < 3; l++) {
        float4 v0 = *(const float4*)(g_of + ((long)w*3 + l)*DD + lane*4);
        float4 v1 = *(const float4*)(g_seq + ((long)w*3 + l)*DD + lane*4);
        float4 v = make_float4(v0.x+v1.x, v0.y+v1.y, v0.z+v1.z, v0.w+v1.w);
        float s  = wrsum(v.x + v.y + v.z + v.w);
        float s2 = wrsum(dot4(v, v));
        float mu  = s * (1.f/128.f);
        float var = s2 * (1.f/128.f) - mu*mu;
        float is = rsqrtf(var + 1e-6f);
        acc.x += g4.x*(v.x - mu)*is + b4.x;
        acc.y += g4.y*(v.y - mu)*is + b4.y;
        acc.z += g4.z*(v.z - mu)*is + b4.z;
        acc.w += g4.w*(v.w - mu)*is + b4.w;
    }
    float4 r = make_float4(acc.x*(1.f/3.f), acc.y*(1.f/3.f),
                           acc.z*(1.f/3.f), acc.w*(1.f/3.f));
    *(float4*)(out + (long)b*NN*256 + (long)row*256 + lane*4) = r;
}

/* ------------------------- bf16-split HMMA GEMM (R8-proven body) -------------- */
#define SLDA 40

__device__ __forceinline__ void mma_bf16(float* d, const uint32_t* a,
                                         const uint32_t* b) {
    asm volatile(
        "mma.sync.aligned.m16n8k16.row.col.f32.bf16.bf16.f32 "
        "{%0,%1,%2,%3}, {%4,%5,%6,%7}, {%8,%9}, {%0,%1,%2,%3};"
        : "+f"(d[0]), "+f"(d[1]), "+f"(d[2]), "+f"(d[3])
        : "r"(a[0]), "r"(a[1]), "r"(a[2]), "r"(a[3]), "r"(b[0]), "r"(b[1]));
}

__device__ __forceinline__ void hmma_body(
    __nv_bfloat16* sAh, __nv_bfloat16* sAl,
    __nv_bfloat16* sBh, __nv_bfloat16* sBl,
    const float* __restrict__ A, int lda,
    const float* __restrict__ Bt, int ldb,
    float* __restrict__ C, int ldc, int M, int K, int bm, int bn) {
    int tid = threadIdx.x, wid = tid >> 5, lane = tid & 31;
    int wm = wid & 3, wn = wid >> 2;
    int g = lane >> 2, tg = lane & 3;

    float acc[2][8][4];
#pragma unroll
    for (int i = 0; i < 2; i++)
#pragma unroll
        for (int j = 0; j < 8; j++)
#pragma unroll
            for (int r = 0; r < 4; r++) acc[i][j][r] = 0.f;

    for (int kc = 0; kc < K; kc += 32) {
#pragma unroll
        for (int it = 0; it < 4; it++) {
            int idx = tid + it*256;
            int r = idx >> 3, c4 = (idx & 7) << 2;
            float4 va = make_float4(0.f, 0.f, 0.f, 0.f);
            if (bm + r < M) va = *(const float4*)(A + (long)(bm+r)*lda + kc + c4);
            __nv_bfloat162 h0 = __float22bfloat162_rn(make_float2(va.x, va.y));
            __nv_bfloat162 h1 = __float22bfloat162_rn(make_float2(va.z, va.w));
            float2 f0 = __bfloat1622float2(h0), f1 = __bfloat1622float2(h1);
            __nv_bfloat162 l0 = __float22bfloat162_rn(make_float2(va.x-f0.x, va.y-f0.y));
            __nv_bfloat162 l1 = __float22bfloat162_rn(make_float2(va.z-f1.x, va.w-f1.y));
            *(uint2*)&sAh[r*SLDA + c4] = make_uint2(*(uint32_t*)&h0, *(uint32_t*)&h1);
            *(uint2*)&sAl[r*SLDA + c4] = make_uint2(*(uint32_t*)&l0, *(uint32_t*)&l1);

            float4 vb = *(const float4*)(Bt + (long)(bn+r)*ldb + kc + c4);
            h0 = __float22bfloat162_rn(make_float2(vb.x, vb.y));
            h1 = __float22bfloat162_rn(make_float2(vb.z, vb.w));
            f0 = __bfloat1622float2(h0); f1 = __bfloat1622float2(h1);
            l0 = __float22bfloat162_rn(make_float2(vb.x-f0.x, vb.y-f0.y));
            l1 = __float22bfloat162_rn(make_float2(vb.z-f1.x, vb.w-f1.y));
            *(uint2*)&sBh[r*SLDA + c4] = make_uint2(*(uint32_t*)&h0, *(uint32_t*)&h1);
            *(uint2*)&sBl[r*SLDA + c4] = make_uint2(*(uint32_t*)&l0, *(uint32_t*)&l1);
        }
        __syncthreads();

#pragma unroll
        for (int ks = 0; ks < 32; ks += 16) {
            uint32_t ah[2][4], al[2][4];
#pragma unroll
            for (int mt = 0; mt < 2; mt++) {
                int r0 = (wm*32 + mt*16 + g) * SLDA + ks + tg*2;
                int r8 = r0 + 8*SLDA;
                ah[mt][0] = *(const uint32_t*)&sAh[r0];
                ah[mt][1] = *(const uint32_t*)&sAh[r8];
                ah[mt][2] = *(const uint32_t*)&sAh[r0 + 8];
                ah[mt][3] = *(const uint32_t*)&sAh[r8 + 8];
                al[mt][0] = *(const uint32_t*)&sAl[r0];
                al[mt][1] = *(const uint32_t*)&sAl[r8];
                al[mt][2] = *(const uint32_t*)&sAl[r0 + 8];
                al[mt][3] = *(const uint32_t*)&sAl[r8 + 8];
            }
#pragma unroll
            for (int nt = 0; nt < 8; nt++) {
                int n0 = (wn*64 + nt*8 + g) * SLDA + ks + tg*2;
                uint32_t bh[2], bl[2];
                bh[0] = *(const uint32_t*)&sBh[n0];
                bh[1] = *(const uint32_t*)&sBh[n0 + 8];
                bl[0] = *(const uint32_t*)&sBl[n0];
                bl[1] = *(const uint32_t*)&sBl[n0 + 8];
                mma_bf16(acc[0][nt], ah[0], bh);
                mma_bf16(acc[1][nt], ah[1], bh);
                mma_bf16(acc[0][nt], ah[0], bl);
                mma_bf16(acc[1][nt], ah[1], bl);
                mma_bf16(acc[0][nt], al[0], bh);
                mma_bf16(acc[1][nt], al[1], bh);
            }
        }
        __syncthreads();
    }

#pragma unroll
    for (int mt = 0; mt < 2; mt++) {
        int r0 = bm + wm*32 + mt*16 + g;
#pragma unroll
        for (int nt = 0; nt < 8; nt++) {
            int c0 = bn + wn*64 + nt*8 + tg*2;
            if (r0 < M)
                *(float2*)(C + (long)r0*ldc + c0) =
                    make_float2(acc[mt][nt][0], acc[mt][nt][1]);
            if (r0 + 8 < M)
                *(float2*)(C + (long)(r0+8)*ldc + c0) =
                    make_float2(acc[mt][nt][2], acc[mt][nt][3]);
        }
    }
}

__global__ void __launch_bounds__(256, 1)
k_hmma(const float* __restrict__ A, int lda,
       const float* __restrict__ Bt, int ldb,
       float* __restrict__ C, int ldc, int M, int K) {
    __shared__ __nv_bfloat16 sAh[128*SLDA], sAl[128*SLDA];
    __shared__ __nv_bfloat16 sBh[128*SLDA], sBl[128*SLDA];
    hmma_body(sAh, sAl, sBh, sBl, A, lda, Bt, ldb, C, ldc, M, K,
              blockIdx.y * 128, blockIdx.x * 128);
}

/* two co-scheduled GEMMs, z selects the job (both N=128, M=12000) ------------- */
__global__ void __launch_bounds__(256, 1)
k_hmma2(const float* __restrict__ A0, int lda0, const float* __restrict__ B0,
        int ldb0, float* __restrict__ C0, int ldc0, int K0,
        const float* __restrict__ A1, int lda1, const float* __restrict__ B1,
        int ldb1, float* __restrict__ C1, int ldc1, int K1) {
    __shared__ __nv_bfloat16 sAh[128*SLDA], sAl[128*SLDA];
    __shared__ __nv_bfloat16 sBh[128*SLDA], sBl[128*SLDA];
    if (blockIdx.z == 0)
        hmma_body(sAh, sAl, sBh, sBl, A0, lda0, B0, ldb0, C0, ldc0,
                  12000, K0, blockIdx.y * 128, 0);
    else
        hmma_body(sAh, sAl, sBh, sBl, A1, lda1, B1, ldb1, C1, ldc1,
                  12000, K1, blockIdx.y * 128, 0);
}

/* ------------------------- host driver ----------------------------------------- */
extern "C" void kernel_launch(void* const* d_in, const int* in_sizes, int n_in,
                              void* d_out, int out_size) {
    const float* ent_sr    = (const float*)d_in[0];
    const float* ent_tg    = (const float*)d_in[1];
    const float* rel_sr    = (const float*)d_in[2];
    const float* rel_tg    = (const float*)d_in[3];
    const float* adj_sr    = (const float*)d_in[4];
    const float* adj_tg    = (const float*)d_in[5];
    const float* rel_adj_sr= (const float*)d_in[6];
    const float* rel_adj_tg= (const float*)d_in[7];
    const float* gat_W     = (const float*)d_in[8];
    const float* gat_a_src = (const float*)d_in[9];
    const float* gat_a_dst = (const float*)d_in[10];
    const float* Wq        = (const float*)d_in[11];
    const float* Wk        = (const float*)d_in[12];
    const float* Wv        = (const float*)d_in[13];
    const float* Wfc       = (const float*)d_in[14];
    const float* ln_g      = (const float*)d_in[15];
    const float* ln_b      = (const float*)d_in[16];
    const float* hgc_W     = (const float*)d_in[17];
    const float* hgc_b     = (const float*)d_in[18];
    float* out = (float*)d_out;

    float *seq, *mix, *mv, *y2, *z, *of, *u, *t, *w, *Gt, *Pt, *Wgt;
    cudaGetSymbolAddress((void**)&seq, g_seq);
    cudaGetSymbolAddress((void**)&mix, g_mix);
    cudaGetSymbolAddress((void**)&mv,  g_mv);
    cudaGetSymbolAddress((void**)&y2,  g_y2);
    cudaGetSymbolAddress((void**)&z,   g_z);
    cudaGetSymbolAddress((void**)&of,  g_of);
    cudaGetSymbolAddress((void**)&u,   g_u);
    cudaGetSymbolAddress((void**)&t,   g_t);
    cudaGetSymbolAddress((void**)&w,   g_w);
    cudaGetSymbolAddress((void**)&Gt,  g_Gt);
    cudaGetSymbolAddress((void**)&Pt,  g_Pt);
    cudaGetSymbolAddress((void**)&Wgt, g_Wgt);

    dim3 gY  (2, 282);     /* [36000,128]@Gt^T  -> N=256 */
    dim3 gOF (1, 282);     /* [36000,256]@Pt^T  -> N=128 */
    dim3 gDual(1, 94, 2);

    /* prep: everything independent in one launch (adj scan hides the rest) */
    k_prep1<<<24280, 256>>>(adj_sr, adj_tg, rel_adj_sr, rel_adj_tg,
                            Wq, Wk, Wv, Wfc, gat_W, gat_a_src, gat_a_dst);
    k_prep2<<<2*NWB, 256>>>(rel_sr, rel_tg, out, ent_sr, ent_tg);

    /* GAT-L0 mix, then GAT-L0 GEMM || HGC-1 GEMM */
    k_gat_mix<<<NWB, 256>>>(0);
    k_hmma2<<<gDual, 256>>>(mix, 256, Wgt, 256, mv, 128, 256,
                            u, 128, hgc_W, 128, t, 128, 128);
    k_pb<<<2*NWB, 256>>>(1, 1, hgc_b);           /* gat_post(L0) || hgc_bias1 */
    k_ma<<<2*NWB, 256>>>(1);                     /* gat_mix(L1) || hgc_agg(y->w) */
    k_hmma2<<<gDual, 256>>>(mix, 256, Wgt + (long)128*256, 256, mv, 128, 256,
                            w, 128, hgc_W + DD*DD, 128, t, 128, 128);
    k_pb<<<2*NWB, 256>>>(2, 0, hgc_b + DD);      /* gat_post(L1) || hgc_bias2 */

    /* MHA chain; final HGC agg rides with k_mha */
    k_hmma<<<gY, 256>>>(seq, 128, Gt, 128, y2, 256, 36000, 128);
    k_mhaF<<<2*NWB, 256>>>(ent_sr, ent_tg, out); /* mha || hgc_agg final */
    k_hmma<<<gOF, 256>>>(z, 256, Pt, 256, of, 128, 36000, 256);
    k_ln<<<NWB, 256>>>(ln_g, ln_b, out);
}